// round 6
// baseline (speedup 1.0000x reference)
#include <cuda_runtime.h>
#include <cuda_bf16.h>
#include <math.h>

// ---------------- problem constants ----------------
#define N_IMG   16384           // B * 2 * NB_DIGITS
#define NPAIR   (N_IMG / 2)
#define NBATCH  4096
#define SUMS    199

typedef unsigned long long ull;

// ---------------- f32x2 packed helpers (Blackwell FFMA2 path) ----------------
__device__ __forceinline__ ull ffma2(ull a, ull b, ull c) {
    ull d;
    asm("fma.rn.f32x2 %0, %1, %2, %3;" : "=l"(d) : "l"(a), "l"(b), "l"(c));
    return d;
}
__device__ __forceinline__ ull pack2(float lo, float hi) {
    ull r;
    asm("mov.b64 %0, {%1, %2};" : "=l"(r) : "f"(lo), "f"(hi));
    return r;
}
__device__ __forceinline__ float2 unpack2(ull v) {
    float2 f;
    asm("mov.b64 {%0, %1}, %2;" : "=f"(f.x), "=f"(f.y) : "l"(v));
    return f;
}

// ---------------- device scratch ----------------
__device__ ull   g_pool1p[(size_t)NPAIR * 864];   // conv1+pool+relu, pair-packed
__device__ ull   g_pool2p[(size_t)NPAIR * 256];   // conv2+pool+relu, pair-packed NCHW
__device__ float g_logp [(size_t)N_IMG * 10];     // per-image log-softmax
__device__ ull   g_cw1p[150];                     // conv1 w, dup-packed
__device__ ull   g_cw2p[2400];                    // conv2 w, dup-packed
__device__ ull   g_w1p[256 * 120];                // fc1 w transposed [k][j], dup-packed
__device__ ull   g_w2p[120 * 84];
__device__ ull   g_w3p[84 * 10];

// ---------------- weight prep: transpose + dup-pack ----------------
__global__ void prep_kernel(const float* __restrict__ c1w, const float* __restrict__ c2w,
                            const float* __restrict__ w1,  const float* __restrict__ w2,
                            const float* __restrict__ w3) {
    int i = blockIdx.x * blockDim.x + threadIdx.x;
    if (i < 150)  { float v = c1w[i]; g_cw1p[i] = pack2(v, v); }
    if (i < 2400) { float v = c2w[i]; g_cw2p[i] = pack2(v, v); }
    if (i < 256 * 120) { int k = i / 120, j = i % 120; float v = w1[j * 256 + k]; g_w1p[i] = pack2(v, v); }
    if (i < 120 * 84)  { int k = i / 84,  j = i % 84;  float v = w2[j * 120 + k]; g_w2p[i] = pack2(v, v); }
    if (i < 84 * 10)   { int k = i / 10,  j = i % 10;  float v = w3[j * 84 + k];  g_w3p[i] = pack2(v, v); }
}

// ---------------- conv1 (1->6, 5x5) + maxpool2 + relu ----------------
// one pair per block, 288 threads = 6 ch x 12 pooled-rows x 4 col-tiles(3 pos)
#define C1_LD(buf, r) { const ull* rp = sp + (r) * 28 + cb; \
    _Pragma("unroll") for (int q = 0; q < 10; q++) buf[q] = rp[q]; }
#define C1_TAP(ky, LO, HI) { _Pragma("unroll") for (int kx = 0; kx < 5; kx++) { \
    ull wq = wc[(ky) * 5 + kx]; \
    _Pragma("unroll") for (int j = 0; j < 3; j++) { \
        acc[j][0] = ffma2(LO[2*j+kx],   wq, acc[j][0]); \
        acc[j][1] = ffma2(LO[2*j+kx+1], wq, acc[j][1]); \
        acc[j][2] = ffma2(HI[2*j+kx],   wq, acc[j][2]); \
        acc[j][3] = ffma2(HI[2*j+kx+1], wq, acc[j][3]); } } }

__global__ __launch_bounds__(288) void conv1_kernel(const float* __restrict__ img,
                                                    const float* __restrict__ b) {
    __shared__ ull   sp[784];
    __shared__ ull   swp[150];
    __shared__ float sb[6];
    int t = threadIdx.x;
    size_t n0 = (size_t)blockIdx.x * 2;
    for (int i = t; i < 784; i += 288)
        sp[i] = pack2(img[n0 * 784 + i], img[n0 * 784 + 784 + i]);
    if (t < 150) swp[t] = g_cw1p[t];
    if (t < 6)   sb[t] = b[t];
    __syncthreads();

    int c = t / 48, rem = t % 48;
    int py = rem >> 2;
    int px0 = 3 * (rem & 3);
    int cb = 2 * px0;
    const ull* wc = swp + c * 25;

    ull A[10], B[10], acc[3][4];
    #pragma unroll
    for (int j = 0; j < 3; j++)
        #pragma unroll
        for (int q = 0; q < 4; q++) acc[j][q] = 0ULL;

    C1_LD(A, 2 * py); C1_LD(B, 2 * py + 1);
    C1_TAP(0, A, B);
    C1_LD(A, 2 * py + 2); C1_TAP(1, B, A);
    C1_LD(B, 2 * py + 3); C1_TAP(2, A, B);
    C1_LD(A, 2 * py + 4); C1_TAP(3, B, A);
    C1_LD(B, 2 * py + 5); C1_TAP(4, A, B);

    float bb = sb[c];
    #pragma unroll
    for (int j = 0; j < 3; j++) {
        float2 a = unpack2(acc[j][0]), c2 = unpack2(acc[j][1]);
        float2 d = unpack2(acc[j][2]), e  = unpack2(acc[j][3]);
        float oA = fmaxf(fmaxf(fmaxf(a.x, c2.x), fmaxf(d.x, e.x)) + bb, 0.f);
        float oB = fmaxf(fmaxf(fmaxf(a.y, c2.y), fmaxf(d.y, e.y)) + bb, 0.f);
        g_pool1p[(size_t)blockIdx.x * 864 + c * 144 + py * 12 + px0 + j] = pack2(oA, oB);
    }
}

// ---------------- conv2 (6->16, 5x5) + maxpool2 + relu ----------------
// 2 pairs per block, 128 threads = 2 pairs x 16 oc x 4 pooled-rows
#define C2_LD(buf, r) { const ull* rp = xc + (r) * 12; \
    _Pragma("unroll") for (int q = 0; q < 12; q++) buf[q] = rp[q]; }
#define C2_TAP(ky, LO, HI) { _Pragma("unroll") for (int kx = 0; kx < 5; kx++) { \
    ull wq = wi[(ky) * 5 + kx]; \
    _Pragma("unroll") for (int pc = 0; pc < 4; pc++) { \
        acc[pc][0] = ffma2(LO[2*pc+kx],   wq, acc[pc][0]); \
        acc[pc][1] = ffma2(LO[2*pc+kx+1], wq, acc[pc][1]); \
        acc[pc][2] = ffma2(HI[2*pc+kx],   wq, acc[pc][2]); \
        acc[pc][3] = ffma2(HI[2*pc+kx+1], wq, acc[pc][3]); } } }

__global__ __launch_bounds__(128) void conv2_kernel(const float* __restrict__ b) {
    __shared__ ull   sp[2][864];
    __shared__ ull   swp[2400];
    __shared__ float sb[16];
    int t = threadIdx.x;
    size_t p0 = (size_t)blockIdx.x * 2;
    for (int i = t; i < 1728; i += 128)
        sp[i / 864][i % 864] = g_pool1p[p0 * 864 + i];
    for (int i = t; i < 2400; i += 128) swp[i] = g_cw2p[i];
    if (t < 16) sb[t] = b[t];
    __syncthreads();

    int pr = t >> 6, u = t & 63;
    int oc = u >> 2, prow = u & 3;
    const ull* xin = sp[pr];
    const ull* wcb = swp + oc * 150;

    ull A[12], B[12], acc[4][4];
    #pragma unroll
    for (int pc = 0; pc < 4; pc++)
        #pragma unroll
        for (int q = 0; q < 4; q++) acc[pc][q] = 0ULL;

    #pragma unroll 1
    for (int ic = 0; ic < 6; ic++) {
        const ull* xc = xin + ic * 144;
        const ull* wi = wcb + ic * 25;
        C2_LD(A, 2 * prow); C2_LD(B, 2 * prow + 1);
        C2_TAP(0, A, B);
        C2_LD(A, 2 * prow + 2); C2_TAP(1, B, A);
        C2_LD(B, 2 * prow + 3); C2_TAP(2, A, B);
        C2_LD(A, 2 * prow + 4); C2_TAP(3, B, A);
        C2_LD(B, 2 * prow + 5); C2_TAP(4, A, B);
    }

    float bb = sb[oc];
    #pragma unroll
    for (int pc = 0; pc < 4; pc++) {
        float2 a = unpack2(acc[pc][0]), c2 = unpack2(acc[pc][1]);
        float2 d = unpack2(acc[pc][2]), e  = unpack2(acc[pc][3]);
        float oA = fmaxf(fmaxf(fmaxf(a.x, c2.x), fmaxf(d.x, e.x)) + bb, 0.f);
        float oB = fmaxf(fmaxf(fmaxf(a.y, c2.y), fmaxf(d.y, e.y)) + bb, 0.f);
        g_pool2p[(p0 + pr) * 256 + oc * 16 + prow * 4 + pc] = pack2(oA, oB);
    }
}

// ---------------- fused FC1+FC2+FC3+log_softmax ----------------
// 8 pairs (16 images) per block, 128 threads; 4-neuron x 2-pair register tiles
#define FCP 8
__global__ __launch_bounds__(128) void fc_kernel(const float* __restrict__ b1,
                                                 const float* __restrict__ b2,
                                                 const float* __restrict__ b3) {
    __shared__ ull xs[FCP][256];
    __shared__ ull h1[FCP][120];
    __shared__ ull h2[FCP][84];
    __shared__ ull h3[FCP][10];
    int t = threadIdx.x;
    size_t p0 = (size_t)blockIdx.x * FCP;
    for (int i = t; i < FCP * 256; i += 128)
        xs[i >> 8][i & 255] = g_pool2p[p0 * 256 + i];
    __syncthreads();

    // ---- layer 1: 256 -> 120, relu; threads: 30 j-tiles x 4 p-tiles ----
    if (t < 120) {
        int jt = t % 30, pt = t / 30;
        int j0 = 4 * jt, pb = 2 * pt;
        float4 bv = *(const float4*)(b1 + j0);
        ull acc[2][4];
        acc[0][0] = acc[1][0] = pack2(bv.x, bv.x);
        acc[0][1] = acc[1][1] = pack2(bv.y, bv.y);
        acc[0][2] = acc[1][2] = pack2(bv.z, bv.z);
        acc[0][3] = acc[1][3] = pack2(bv.w, bv.w);
        #pragma unroll 2
        for (int k = 0; k < 256; k += 2) {
            ulonglong2 x0 = *reinterpret_cast<const ulonglong2*>(&xs[pb][k]);
            ulonglong2 x1 = *reinterpret_cast<const ulonglong2*>(&xs[pb + 1][k]);
            const ulonglong2* wp0 = reinterpret_cast<const ulonglong2*>(&g_w1p[(size_t)k * 120 + j0]);
            const ulonglong2* wp1 = reinterpret_cast<const ulonglong2*>(&g_w1p[(size_t)(k + 1) * 120 + j0]);
            ulonglong2 wa = wp0[0], wb = wp0[1];
            ulonglong2 wc = wp1[0], wd = wp1[1];
            acc[0][0] = ffma2(x0.x, wa.x, acc[0][0]);
            acc[0][1] = ffma2(x0.x, wa.y, acc[0][1]);
            acc[0][2] = ffma2(x0.x, wb.x, acc[0][2]);
            acc[0][3] = ffma2(x0.x, wb.y, acc[0][3]);
            acc[1][0] = ffma2(x1.x, wa.x, acc[1][0]);
            acc[1][1] = ffma2(x1.x, wa.y, acc[1][1]);
            acc[1][2] = ffma2(x1.x, wb.x, acc[1][2]);
            acc[1][3] = ffma2(x1.x, wb.y, acc[1][3]);
            acc[0][0] = ffma2(x0.y, wc.x, acc[0][0]);
            acc[0][1] = ffma2(x0.y, wc.y, acc[0][1]);
            acc[0][2] = ffma2(x0.y, wd.x, acc[0][2]);
            acc[0][3] = ffma2(x0.y, wd.y, acc[0][3]);
            acc[1][0] = ffma2(x1.y, wc.x, acc[1][0]);
            acc[1][1] = ffma2(x1.y, wc.y, acc[1][1]);
            acc[1][2] = ffma2(x1.y, wd.x, acc[1][2]);
            acc[1][3] = ffma2(x1.y, wd.y, acc[1][3]);
        }
        #pragma unroll
        for (int p = 0; p < 2; p++)
            #pragma unroll
            for (int n = 0; n < 4; n++) {
                float2 u = unpack2(acc[p][n]);
                h1[pb + p][j0 + n] = pack2(fmaxf(u.x, 0.f), fmaxf(u.y, 0.f));
            }
    }
    __syncthreads();

    // ---- layer 2: 120 -> 84, relu; threads: 21 j-tiles x 4 p-tiles ----
    if (t < 84) {
        int jt = t % 21, pt = t / 21;
        int j0 = 4 * jt, pb = 2 * pt;
        float4 bv = *(const float4*)(b2 + j0);
        ull acc[2][4];
        acc[0][0] = acc[1][0] = pack2(bv.x, bv.x);
        acc[0][1] = acc[1][1] = pack2(bv.y, bv.y);
        acc[0][2] = acc[1][2] = pack2(bv.z, bv.z);
        acc[0][3] = acc[1][3] = pack2(bv.w, bv.w);
        #pragma unroll 2
        for (int k = 0; k < 120; k += 2) {
            ulonglong2 x0 = *reinterpret_cast<const ulonglong2*>(&h1[pb][k]);
            ulonglong2 x1 = *reinterpret_cast<const ulonglong2*>(&h1[pb + 1][k]);
            const ulonglong2* wp0 = reinterpret_cast<const ulonglong2*>(&g_w2p[(size_t)k * 84 + j0]);
            const ulonglong2* wp1 = reinterpret_cast<const ulonglong2*>(&g_w2p[(size_t)(k + 1) * 84 + j0]);
            ulonglong2 wa = wp0[0], wb = wp0[1];
            ulonglong2 wc = wp1[0], wd = wp1[1];
            acc[0][0] = ffma2(x0.x, wa.x, acc[0][0]);
            acc[0][1] = ffma2(x0.x, wa.y, acc[0][1]);
            acc[0][2] = ffma2(x0.x, wb.x, acc[0][2]);
            acc[0][3] = ffma2(x0.x, wb.y, acc[0][3]);
            acc[1][0] = ffma2(x1.x, wa.x, acc[1][0]);
            acc[1][1] = ffma2(x1.x, wa.y, acc[1][1]);
            acc[1][2] = ffma2(x1.x, wb.x, acc[1][2]);
            acc[1][3] = ffma2(x1.x, wb.y, acc[1][3]);
            acc[0][0] = ffma2(x0.y, wc.x, acc[0][0]);
            acc[0][1] = ffma2(x0.y, wc.y, acc[0][1]);
            acc[0][2] = ffma2(x0.y, wd.x, acc[0][2]);
            acc[0][3] = ffma2(x0.y, wd.y, acc[0][3]);
            acc[1][0] = ffma2(x1.y, wc.x, acc[1][0]);
            acc[1][1] = ffma2(x1.y, wc.y, acc[1][1]);
            acc[1][2] = ffma2(x1.y, wd.x, acc[1][2]);
            acc[1][3] = ffma2(x1.y, wd.y, acc[1][3]);
        }
        #pragma unroll
        for (int p = 0; p < 2; p++)
            #pragma unroll
            for (int n = 0; n < 4; n++) {
                float2 u = unpack2(acc[p][n]);
                h2[pb + p][j0 + n] = pack2(fmaxf(u.x, 0.f), fmaxf(u.y, 0.f));
            }
    }
    __syncthreads();

    // ---- layer 3: 84 -> 10 (no relu) ----
    if (t < 80) {
        int p = t / 10, d = t % 10;
        float bb = b3[d];
        ull acc = pack2(bb, bb);
        #pragma unroll 4
        for (int k = 0; k < 84; k++)
            acc = ffma2(h2[p][k], g_w3p[k * 10 + d], acc);
        h3[p][d] = acc;
    }
    __syncthreads();

    // ---- log-softmax per image ----
    if (t < 16) {
        int p = t >> 1, hf = t & 1;
        float v[10];
        #pragma unroll
        for (int d = 0; d < 10; d++) {
            float2 u = unpack2(h3[p][d]);
            v[d] = hf ? u.y : u.x;
        }
        float m = -1e30f;
        #pragma unroll
        for (int d = 0; d < 10; d++) m = fmaxf(m, v[d]);
        float s = 0.f;
        #pragma unroll
        for (int d = 0; d < 10; d++) s += __expf(v[d] - m);
        float lse = m + __logf(s);
        float* op = g_logp + (size_t)((p0 + p) * 2 + hf) * 10;
        #pragma unroll
        for (int d = 0; d < 10; d++) op[d] = v[d] - lse;
    }
}

// ---------------- probabilistic circuit: segment logsumexp over i+j=s ---------
__global__ __launch_bounds__(256) void circuit_kernel(float* __restrict__ out) {
    __shared__ float lp[40];
    __shared__ float lp1[100];
    __shared__ float lp2[100];
    int bI = blockIdx.x;
    int t = threadIdx.x;
    if (t < 40) lp[t] = g_logp[(size_t)bI * 40 + t];
    __syncthreads();
    if (t < 100) {
        lp1[t] = lp[0 + t / 10] + lp[10 + t % 10];
    } else if (t < 200) {
        int k = t - 100;
        lp2[k] = lp[20 + k / 10] + lp[30 + k % 10];
    }
    __syncthreads();
    if (t < SUMS) {
        int lo = t > 99 ? t - 99 : 0;
        int hi = t < 99 ? t : 99;
        float m = -1e30f;
        for (int i = lo; i <= hi; i++) m = fmaxf(m, lp1[i] + lp2[t - i]);
        float s = 0.f;
        for (int i = lo; i <= hi; i++) s += __expf(lp1[i] + lp2[t - i] - m);
        out[(size_t)bI * SUMS + t] = m + __logf(s);
    }
}

// ---------------- launch ----------------
extern "C" void kernel_launch(void* const* d_in, const int* in_sizes, int n_in,
                              void* d_out, int out_size) {
    const float* images = (const float*)d_in[0];
    const float* c1w    = (const float*)d_in[1];
    const float* c1b    = (const float*)d_in[2];
    const float* c2w    = (const float*)d_in[3];
    const float* c2b    = (const float*)d_in[4];
    const float* f1w    = (const float*)d_in[5];
    const float* f1b    = (const float*)d_in[6];
    const float* f2w    = (const float*)d_in[7];
    const float* f2b    = (const float*)d_in[8];
    const float* f3w    = (const float*)d_in[9];
    const float* f3b    = (const float*)d_in[10];
    float* out = (float*)d_out;

    prep_kernel<<<120, 256>>>(c1w, c2w, f1w, f2w, f3w);
    conv1_kernel<<<NPAIR, 288>>>(images, c1b);
    conv2_kernel<<<NPAIR / 2, 128>>>(c2b);
    fc_kernel<<<NPAIR / FCP, 128>>>(f1b, f2b, f3b);
    circuit_kernel<<<NBATCH, 256>>>(out);
}

// round 8
// speedup vs baseline: 1.7460x; 1.7460x over previous
#include <cuda_runtime.h>
#include <cuda_bf16.h>
#include <math.h>

// ---------------- problem constants ----------------
#define N_IMG   16384           // B * 2 * NB_DIGITS
#define NPAIR   (N_IMG / 2)
#define NBATCH  4096
#define SUMS    199

typedef unsigned long long ull;

// ---------------- f32x2 packed helpers (Blackwell FFMA2 path) ----------------
__device__ __forceinline__ ull ffma2(ull a, ull b, ull c) {
    ull d;
    asm("fma.rn.f32x2 %0, %1, %2, %3;" : "=l"(d) : "l"(a), "l"(b), "l"(c));
    return d;
}
__device__ __forceinline__ ull pack2(float lo, float hi) {
    ull r;
    asm("mov.b64 %0, {%1, %2};" : "=l"(r) : "f"(lo), "f"(hi));
    return r;
}
__device__ __forceinline__ float2 unpack2(ull v) {
    float2 f;
    asm("mov.b64 {%0, %1}, %2;" : "=f"(f.x), "=f"(f.y) : "l"(v));
    return f;
}

// ---------------- device scratch ----------------
__device__ ull    g_pool1p[(size_t)NPAIR * 864];  // conv1+pool+relu, pair-packed
__device__ ull    g_pool2p[(size_t)NPAIR * 256];  // conv2+pool+relu, pair-packed NCHW
__device__ float  g_logp [(size_t)N_IMG * 10];    // per-image log-softmax
__device__ float2 g_w1v[128 * 120];               // fc1 w: [k/2][j] -> {w[k][j], w[k+1][j]}
__device__ float2 g_w2v[60 * 84];                 // fc2 w interleaved same way
__device__ float  g_w3t[84 * 10];                 // fc3 w transposed [k][j]

// ---------------- weight prep: transpose + k-pair interleave ----------------
__global__ void prep_kernel(const float* __restrict__ w1, const float* __restrict__ w2,
                            const float* __restrict__ w3) {
    int i = blockIdx.x * blockDim.x + threadIdx.x;
    if (i < 128 * 120) {
        int kk = i / 120, j = i % 120;
        g_w1v[i] = make_float2(w1[j * 256 + 2 * kk], w1[j * 256 + 2 * kk + 1]);
    }
    if (i < 60 * 84) {
        int kk = i / 84, j = i % 84;
        g_w2v[i] = make_float2(w2[j * 120 + 2 * kk], w2[j * 120 + 2 * kk + 1]);
    }
    if (i < 84 * 10) {
        int k = i / 10, j = i % 10;
        g_w3t[i] = w3[j * 84 + k];
    }
}

// ---------------- conv1 (1->6, 5x5) + maxpool2 + relu ----------------
// 4 pairs (8 images) per block, 576 threads = 4 pairs x 144 pooled positions
__global__ __launch_bounds__(576) void conv1_kernel(const float* __restrict__ img,
                                                    const float* __restrict__ w,
                                                    const float* __restrict__ b) {
    __shared__ ull   sp[4][784];
    __shared__ ull   swp[150];
    __shared__ float sb[6];
    int t = threadIdx.x;
    size_t n0 = (size_t)blockIdx.x * 8;           // first image
    for (int i = t; i < 4 * 784; i += 576) {
        int q = i / 784, j = i % 784;
        sp[q][j] = pack2(img[(n0 + 2 * q) * 784 + j],
                         img[(n0 + 2 * q + 1) * 784 + j]);
    }
    if (t < 150) { float v = w[t]; swp[t] = pack2(v, v); }
    if (t < 6)   sb[t] = b[t];
    __syncthreads();

    int pairIdx = t / 144;                        // 0..3
    int pos = t % 144;
    int py = pos / 12, px = pos % 12;
    const ull* si = sp[pairIdx];

    ull acc[6][4];
    #pragma unroll
    for (int ic = 0; ic < 6; ic++)
        #pragma unroll
        for (int q = 0; q < 4; q++) acc[ic][q] = 0ULL;

    #pragma unroll
    for (int ky = 0; ky < 5; ky++) {
        #pragma unroll
        for (int kx = 0; kx < 5; kx++) {
            int base = (2 * py + ky) * 28 + 2 * px + kx;
            ull x00 = si[base],      x01 = si[base + 1];
            ull x10 = si[base + 28], x11 = si[base + 29];
            #pragma unroll
            for (int ic = 0; ic < 6; ic++) {
                ull wq = swp[ic * 25 + ky * 5 + kx];
                acc[ic][0] = ffma2(x00, wq, acc[ic][0]);
                acc[ic][1] = ffma2(x01, wq, acc[ic][1]);
                acc[ic][2] = ffma2(x10, wq, acc[ic][2]);
                acc[ic][3] = ffma2(x11, wq, acc[ic][3]);
            }
        }
    }

    size_t pg = (size_t)blockIdx.x * 4 + pairIdx;
    #pragma unroll
    for (int ic = 0; ic < 6; ic++) {
        float2 a = unpack2(acc[ic][0]), c2 = unpack2(acc[ic][1]);
        float2 d = unpack2(acc[ic][2]), e  = unpack2(acc[ic][3]);
        float bb = sb[ic];
        float oA = fmaxf(fmaxf(fmaxf(a.x, c2.x), fmaxf(d.x, e.x)) + bb, 0.f);
        float oB = fmaxf(fmaxf(fmaxf(a.y, c2.y), fmaxf(d.y, e.y)) + bb, 0.f);
        g_pool1p[pg * 864 + ic * 144 + pos] = pack2(oA, oB);
    }
}

// ---------------- conv2 (6->16, 5x5) + maxpool2 + relu ----------------
// 4 pairs (8 images) per block, 128 threads = 4 pairs x 2 ch-groups x 16 pooled pos
__global__ __launch_bounds__(128) void conv2_kernel(const float* __restrict__ w,
                                                    const float* __restrict__ b) {
    __shared__ ull   sp[4][864];
    __shared__ ull   swp[2400];
    __shared__ float sb[16];
    int t = threadIdx.x;
    size_t p0 = (size_t)blockIdx.x * 4;
    for (int i = t; i < 4 * 864; i += 128)
        sp[i / 864][i % 864] = g_pool1p[p0 * 864 + i];
    for (int i = t; i < 2400; i += 128) { float v = w[i]; swp[i] = pack2(v, v); }
    if (t < 16) sb[t] = b[t];
    __syncthreads();

    int pr  = t >> 5;                 // pair 0..3
    int sub = t & 31;
    int pos = sub & 15;
    int cg  = sub >> 4;
    int py = pos >> 2, px = pos & 3;
    int c0 = cg * 8;
    const ull* si = sp[pr];

    ull acc[8][4];
    #pragma unroll
    for (int cc = 0; cc < 8; cc++)
        #pragma unroll
        for (int q = 0; q < 4; q++) acc[cc][q] = 0ULL;

    #pragma unroll 1
    for (int ic = 0; ic < 6; ic++) {
        const ull* xi = si + ic * 144;
        const ull* wi = swp + c0 * 150 + ic * 25;
        #pragma unroll
        for (int ky = 0; ky < 5; ky++) {
            #pragma unroll
            for (int kx = 0; kx < 5; kx++) {
                int base = (2 * py + ky) * 12 + 2 * px + kx;
                ull x00 = xi[base],      x01 = xi[base + 1];
                ull x10 = xi[base + 12], x11 = xi[base + 13];
                #pragma unroll
                for (int cc = 0; cc < 8; cc++) {
                    ull wq = wi[cc * 150 + ky * 5 + kx];
                    acc[cc][0] = ffma2(x00, wq, acc[cc][0]);
                    acc[cc][1] = ffma2(x01, wq, acc[cc][1]);
                    acc[cc][2] = ffma2(x10, wq, acc[cc][2]);
                    acc[cc][3] = ffma2(x11, wq, acc[cc][3]);
                }
            }
        }
    }

    #pragma unroll
    for (int cc = 0; cc < 8; cc++) {
        float2 a = unpack2(acc[cc][0]), c2 = unpack2(acc[cc][1]);
        float2 d = unpack2(acc[cc][2]), e  = unpack2(acc[cc][3]);
        float bb = sb[c0 + cc];
        float oA = fmaxf(fmaxf(fmaxf(a.x, c2.x), fmaxf(d.x, e.x)) + bb, 0.f);
        float oB = fmaxf(fmaxf(fmaxf(a.y, c2.y), fmaxf(d.y, e.y)) + bb, 0.f);
        g_pool2p[(p0 + pr) * 256 + (c0 + cc) * 16 + py * 4 + px] = pack2(oA, oB);
    }
}

// ---------------- fused FC1+FC2+FC3+log_softmax ----------------
// 8 pairs (16 images) per block, 128 threads; thread j owns neuron j for 8 pairs
#define FCP 8
__global__ __launch_bounds__(128) void fc_kernel(const float* __restrict__ b1,
                                                 const float* __restrict__ b2,
                                                 const float* __restrict__ b3) {
    __shared__ __align__(16) ull xs[FCP][256];
    __shared__ __align__(16) ull h1[FCP][120];
    __shared__ __align__(16) ull h2[FCP][84];
    __shared__ ull h3[FCP][10];
    int t = threadIdx.x;
    size_t p0 = (size_t)blockIdx.x * FCP;
    for (int i = t; i < FCP * 256; i += 128)
        xs[i >> 8][i & 255] = g_pool2p[p0 * 256 + i];
    __syncthreads();

    // ---- layer 1: 256 -> 120, relu ----
    if (t < 120) {
        float bb = b1[t];
        ull bp = pack2(bb, bb);
        ull acc[FCP];
        #pragma unroll
        for (int p = 0; p < FCP; p++) acc[p] = bp;
        #pragma unroll 4
        for (int kk = 0; kk < 128; kk++) {
            float2 wv = g_w1v[kk * 120 + t];
            ull wq0 = pack2(wv.x, wv.x);
            ull wq1 = pack2(wv.y, wv.y);
            #pragma unroll
            for (int p = 0; p < FCP; p++) {
                ulonglong2 xv = *reinterpret_cast<const ulonglong2*>(&xs[p][2 * kk]);
                acc[p] = ffma2(xv.x, wq0, acc[p]);
                acc[p] = ffma2(xv.y, wq1, acc[p]);
            }
        }
        #pragma unroll
        for (int p = 0; p < FCP; p++) {
            float2 u = unpack2(acc[p]);
            h1[p][t] = pack2(fmaxf(u.x, 0.f), fmaxf(u.y, 0.f));
        }
    }
    __syncthreads();

    // ---- layer 2: 120 -> 84, relu ----
    if (t < 84) {
        float bb = b2[t];
        ull bp = pack2(bb, bb);
        ull acc[FCP];
        #pragma unroll
        for (int p = 0; p < FCP; p++) acc[p] = bp;
        #pragma unroll 4
        for (int kk = 0; kk < 60; kk++) {
            float2 wv = g_w2v[kk * 84 + t];
            ull wq0 = pack2(wv.x, wv.x);
            ull wq1 = pack2(wv.y, wv.y);
            #pragma unroll
            for (int p = 0; p < FCP; p++) {
                ulonglong2 xv = *reinterpret_cast<const ulonglong2*>(&h1[p][2 * kk]);
                acc[p] = ffma2(xv.x, wq0, acc[p]);
                acc[p] = ffma2(xv.y, wq1, acc[p]);
            }
        }
        #pragma unroll
        for (int p = 0; p < FCP; p++) {
            float2 u = unpack2(acc[p]);
            h2[p][t] = pack2(fmaxf(u.x, 0.f), fmaxf(u.y, 0.f));
        }
    }
    __syncthreads();

    // ---- layer 3: 84 -> 10 (no relu) ----
    if (t < 80) {
        int p = t / 10, d = t % 10;
        float bb = b3[d];
        ull acc = pack2(bb, bb);
        #pragma unroll 4
        for (int k = 0; k < 84; k++) {
            float wv = g_w3t[k * 10 + d];
            acc = ffma2(h2[p][k], pack2(wv, wv), acc);
        }
        h3[p][d] = acc;
    }
    __syncthreads();

    // ---- log-softmax per image ----
    if (t < 16) {
        int p = t >> 1, hf = t & 1;
        float v[10];
        #pragma unroll
        for (int d = 0; d < 10; d++) {
            float2 u = unpack2(h3[p][d]);
            v[d] = hf ? u.y : u.x;
        }
        float m = -1e30f;
        #pragma unroll
        for (int d = 0; d < 10; d++) m = fmaxf(m, v[d]);
        float s = 0.f;
        #pragma unroll
        for (int d = 0; d < 10; d++) s += __expf(v[d] - m);
        float lse = m + __logf(s);
        float* op = g_logp + (size_t)((p0 + p) * 2 + hf) * 10;
        #pragma unroll
        for (int d = 0; d < 10; d++) op[d] = v[d] - lse;
    }
}

// ---------------- probabilistic circuit: segment logsumexp over i+j=s ---------
__global__ __launch_bounds__(256) void circuit_kernel(float* __restrict__ out) {
    __shared__ float lp[40];
    __shared__ float lp1[100];
    __shared__ float lp2[100];
    int bI = blockIdx.x;
    int t = threadIdx.x;
    if (t < 40) lp[t] = g_logp[(size_t)bI * 40 + t];
    __syncthreads();
    if (t < 100) {
        lp1[t] = lp[0 + t / 10] + lp[10 + t % 10];
    } else if (t < 200) {
        int k = t - 100;
        lp2[k] = lp[20 + k / 10] + lp[30 + k % 10];
    }
    __syncthreads();
    if (t < SUMS) {
        int lo = t > 99 ? t - 99 : 0;
        int hi = t < 99 ? t : 99;
        float m = -1e30f;
        for (int i = lo; i <= hi; i++) m = fmaxf(m, lp1[i] + lp2[t - i]);
        float s = 0.f;
        for (int i = lo; i <= hi; i++) s += __expf(lp1[i] + lp2[t - i] - m);
        out[(size_t)bI * SUMS + t] = m + __logf(s);
    }
}

// ---------------- launch ----------------
extern "C" void kernel_launch(void* const* d_in, const int* in_sizes, int n_in,
                              void* d_out, int out_size) {
    const float* images = (const float*)d_in[0];
    const float* c1w    = (const float*)d_in[1];
    const float* c1b    = (const float*)d_in[2];
    const float* c2w    = (const float*)d_in[3];
    const float* c2b    = (const float*)d_in[4];
    const float* f1w    = (const float*)d_in[5];
    const float* f1b    = (const float*)d_in[6];
    const float* f2w    = (const float*)d_in[7];
    const float* f2b    = (const float*)d_in[8];
    const float* f3w    = (const float*)d_in[9];
    const float* f3b    = (const float*)d_in[10];
    float* out = (float*)d_out;

    prep_kernel<<<60, 256>>>(f1w, f2w, f3w);
    conv1_kernel<<<NPAIR / 4, 576>>>(images, c1w, c1b);
    conv2_kernel<<<NPAIR / 4, 128>>>(c2w, c2b);
    fc_kernel<<<NPAIR / FCP, 128>>>(f1b, f2b, f3b);
    circuit_kernel<<<NBATCH, 256>>>(out);
}

// round 9
// speedup vs baseline: 1.7711x; 1.0144x over previous
#include <cuda_runtime.h>
#include <cuda_bf16.h>
#include <math.h>

// ---------------- problem constants ----------------
#define N_IMG   16384           // B * 2 * NB_DIGITS
#define NPAIR   (N_IMG / 2)
#define NBATCH  4096
#define SUMS    199

typedef unsigned long long ull;

// ---------------- f32x2 packed helpers (Blackwell FFMA2 path) ----------------
__device__ __forceinline__ ull ffma2(ull a, ull b, ull c) {
    ull d;
    asm("fma.rn.f32x2 %0, %1, %2, %3;" : "=l"(d) : "l"(a), "l"(b), "l"(c));
    return d;
}
__device__ __forceinline__ ull pack2(float lo, float hi) {
    ull r;
    asm("mov.b64 %0, {%1, %2};" : "=l"(r) : "f"(lo), "f"(hi));
    return r;
}
__device__ __forceinline__ float2 unpack2(ull v) {
    float2 f;
    asm("mov.b64 {%0, %1}, %2;" : "=f"(f.x), "=f"(f.y) : "l"(v));
    return f;
}

// ---------------- device scratch ----------------
__device__ ull    g_pool1p[(size_t)NPAIR * 864];  // conv1+pool+relu, pair-packed
__device__ ull    g_pool2p[(size_t)NPAIR * 256];  // conv2+pool+relu, pair-packed NCHW
__device__ float  g_logp [(size_t)N_IMG * 10];    // per-image log-softmax
__device__ float2 g_w1v[128 * 120];               // fc1 w: [k/2][j] -> {w[k][j], w[k+1][j]}
__device__ float2 g_w2v[60 * 84];                 // fc2 w interleaved same way
__device__ float  g_w3t[84 * 10];                 // fc3 w transposed [k][j]

// ---------------- weight prep: transpose + k-pair interleave ----------------
__global__ void prep_kernel(const float* __restrict__ w1, const float* __restrict__ w2,
                            const float* __restrict__ w3) {
    int i = blockIdx.x * blockDim.x + threadIdx.x;
    if (i < 128 * 120) {
        int kk = i / 120, j = i % 120;
        g_w1v[i] = make_float2(w1[j * 256 + 2 * kk], w1[j * 256 + 2 * kk + 1]);
    }
    if (i < 60 * 84) {
        int kk = i / 84, j = i % 84;
        g_w2v[i] = make_float2(w2[j * 120 + 2 * kk], w2[j * 120 + 2 * kk + 1]);
    }
    if (i < 84 * 10) {
        int k = i / 10, j = i % 10;
        g_w3t[i] = w3[j * 84 + k];
    }
}

// ---------------- conv1 (1->6, 5x5) + maxpool2 + relu ----------------
// 4 pairs (8 images) per block, 576 threads = 4 pairs x 144 pooled positions
__global__ __launch_bounds__(576) void conv1_kernel(const float* __restrict__ img,
                                                    const float* __restrict__ w,
                                                    const float* __restrict__ b) {
    __shared__ ull   sp[4][784];
    __shared__ ull   swp[150];
    __shared__ float sb[6];
    int t = threadIdx.x;
    size_t n0 = (size_t)blockIdx.x * 8;           // first image
    for (int i = t; i < 4 * 784; i += 576) {
        int q = i / 784, j = i % 784;
        sp[q][j] = pack2(img[(n0 + 2 * q) * 784 + j],
                         img[(n0 + 2 * q + 1) * 784 + j]);
    }
    if (t < 150) { float v = w[t]; swp[t] = pack2(v, v); }
    if (t < 6)   sb[t] = b[t];
    __syncthreads();

    int pairIdx = t / 144;                        // 0..3
    int pos = t % 144;
    int py = pos / 12, px = pos % 12;
    const ull* si = sp[pairIdx];

    ull acc[6][4];
    #pragma unroll
    for (int ic = 0; ic < 6; ic++)
        #pragma unroll
        for (int q = 0; q < 4; q++) acc[ic][q] = 0ULL;

    #pragma unroll
    for (int ky = 0; ky < 5; ky++) {
        #pragma unroll
        for (int kx = 0; kx < 5; kx++) {
            int base = (2 * py + ky) * 28 + 2 * px + kx;
            ull x00 = si[base],      x01 = si[base + 1];
            ull x10 = si[base + 28], x11 = si[base + 29];
            #pragma unroll
            for (int ic = 0; ic < 6; ic++) {
                ull wq = swp[ic * 25 + ky * 5 + kx];
                acc[ic][0] = ffma2(x00, wq, acc[ic][0]);
                acc[ic][1] = ffma2(x01, wq, acc[ic][1]);
                acc[ic][2] = ffma2(x10, wq, acc[ic][2]);
                acc[ic][3] = ffma2(x11, wq, acc[ic][3]);
            }
        }
    }

    size_t pg = (size_t)blockIdx.x * 4 + pairIdx;
    #pragma unroll
    for (int ic = 0; ic < 6; ic++) {
        float2 a = unpack2(acc[ic][0]), c2 = unpack2(acc[ic][1]);
        float2 d = unpack2(acc[ic][2]), e  = unpack2(acc[ic][3]);
        float bb = sb[ic];
        float oA = fmaxf(fmaxf(fmaxf(a.x, c2.x), fmaxf(d.x, e.x)) + bb, 0.f);
        float oB = fmaxf(fmaxf(fmaxf(a.y, c2.y), fmaxf(d.y, e.y)) + bb, 0.f);
        g_pool1p[pg * 864 + ic * 144 + pos] = pack2(oA, oB);
    }
}

// ---------------- conv2 (6->16, 5x5) + maxpool2 + relu ----------------
// 8 pairs (16 images) per block, 256 threads = 8 pairs x 2 ch-groups x 16 pooled pos
__global__ __launch_bounds__(256) void conv2_kernel(const float* __restrict__ w,
                                                    const float* __restrict__ b) {
    __shared__ ull   sp[8][864];
    __shared__ ull   swp[2400];
    __shared__ float sb[16];
    int t = threadIdx.x;
    size_t p0 = (size_t)blockIdx.x * 8;
    for (int i = t; i < 8 * 864; i += 256)
        sp[i / 864][i % 864] = g_pool1p[p0 * 864 + i];
    for (int i = t; i < 2400; i += 256) { float v = w[i]; swp[i] = pack2(v, v); }
    if (t < 16) sb[t] = b[t];
    __syncthreads();

    int pr  = t >> 5;                 // pair 0..7
    int sub = t & 31;
    int pos = sub & 15;
    int cg  = sub >> 4;
    int py = pos >> 2, px = pos & 3;
    int c0 = cg * 8;
    const ull* si = sp[pr];

    ull acc[8][4];
    #pragma unroll
    for (int cc = 0; cc < 8; cc++)
        #pragma unroll
        for (int q = 0; q < 4; q++) acc[cc][q] = 0ULL;

    #pragma unroll 1
    for (int ic = 0; ic < 6; ic++) {
        const ull* xi = si + ic * 144;
        const ull* wi = swp + c0 * 150 + ic * 25;
        #pragma unroll
        for (int ky = 0; ky < 5; ky++) {
            #pragma unroll
            for (int kx = 0; kx < 5; kx++) {
                int base = (2 * py + ky) * 12 + 2 * px + kx;
                ull x00 = xi[base],      x01 = xi[base + 1];
                ull x10 = xi[base + 12], x11 = xi[base + 13];
                #pragma unroll
                for (int cc = 0; cc < 8; cc++) {
                    ull wq = wi[cc * 150 + ky * 5 + kx];
                    acc[cc][0] = ffma2(x00, wq, acc[cc][0]);
                    acc[cc][1] = ffma2(x01, wq, acc[cc][1]);
                    acc[cc][2] = ffma2(x10, wq, acc[cc][2]);
                    acc[cc][3] = ffma2(x11, wq, acc[cc][3]);
                }
            }
        }
    }

    #pragma unroll
    for (int cc = 0; cc < 8; cc++) {
        float2 a = unpack2(acc[cc][0]), c2 = unpack2(acc[cc][1]);
        float2 d = unpack2(acc[cc][2]), e  = unpack2(acc[cc][3]);
        float bb = sb[c0 + cc];
        float oA = fmaxf(fmaxf(fmaxf(a.x, c2.x), fmaxf(d.x, e.x)) + bb, 0.f);
        float oB = fmaxf(fmaxf(fmaxf(a.y, c2.y), fmaxf(d.y, e.y)) + bb, 0.f);
        g_pool2p[(p0 + pr) * 256 + (c0 + cc) * 16 + py * 4 + px] = pack2(oA, oB);
    }
}

// ---------------- fused FC1+FC2+FC3+log_softmax ----------------
// 8 pairs (16 images) per block, 128 threads; thread j owns neuron j for 8 pairs
#define FCP 8
__global__ __launch_bounds__(128) void fc_kernel(const float* __restrict__ b1,
                                                 const float* __restrict__ b2,
                                                 const float* __restrict__ b3) {
    __shared__ __align__(16) ull xs[FCP][256];
    __shared__ __align__(16) ull h1[FCP][120];
    __shared__ __align__(16) ull h2[FCP][84];
    __shared__ ull h3[FCP][10];
    int t = threadIdx.x;
    size_t p0 = (size_t)blockIdx.x * FCP;
    for (int i = t; i < FCP * 256; i += 128)
        xs[i >> 8][i & 255] = g_pool2p[p0 * 256 + i];
    __syncthreads();

    // ---- layer 1: 256 -> 120, relu ----
    if (t < 120) {
        float bb = b1[t];
        ull bp = pack2(bb, bb);
        ull acc[FCP];
        #pragma unroll
        for (int p = 0; p < FCP; p++) acc[p] = bp;
        #pragma unroll 8
        for (int kk = 0; kk < 128; kk++) {
            float2 wv = g_w1v[kk * 120 + t];
            ull wq0 = pack2(wv.x, wv.x);
            ull wq1 = pack2(wv.y, wv.y);
            #pragma unroll
            for (int p = 0; p < FCP; p++) {
                ulonglong2 xv = *reinterpret_cast<const ulonglong2*>(&xs[p][2 * kk]);
                acc[p] = ffma2(xv.x, wq0, acc[p]);
                acc[p] = ffma2(xv.y, wq1, acc[p]);
            }
        }
        #pragma unroll
        for (int p = 0; p < FCP; p++) {
            float2 u = unpack2(acc[p]);
            h1[p][t] = pack2(fmaxf(u.x, 0.f), fmaxf(u.y, 0.f));
        }
    }
    __syncthreads();

    // ---- layer 2: 120 -> 84, relu ----
    if (t < 84) {
        float bb = b2[t];
        ull bp = pack2(bb, bb);
        ull acc[FCP];
        #pragma unroll
        for (int p = 0; p < FCP; p++) acc[p] = bp;
        #pragma unroll 6
        for (int kk = 0; kk < 60; kk++) {
            float2 wv = g_w2v[kk * 84 + t];
            ull wq0 = pack2(wv.x, wv.x);
            ull wq1 = pack2(wv.y, wv.y);
            #pragma unroll
            for (int p = 0; p < FCP; p++) {
                ulonglong2 xv = *reinterpret_cast<const ulonglong2*>(&h1[p][2 * kk]);
                acc[p] = ffma2(xv.x, wq0, acc[p]);
                acc[p] = ffma2(xv.y, wq1, acc[p]);
            }
        }
        #pragma unroll
        for (int p = 0; p < FCP; p++) {
            float2 u = unpack2(acc[p]);
            h2[p][t] = pack2(fmaxf(u.x, 0.f), fmaxf(u.y, 0.f));
        }
    }
    __syncthreads();

    // ---- layer 3: 84 -> 10 (no relu) ----
    if (t < 80) {
        int p = t / 10, d = t % 10;
        float bb = b3[d];
        ull acc = pack2(bb, bb);
        #pragma unroll 4
        for (int k = 0; k < 84; k++) {
            float wv = g_w3t[k * 10 + d];
            acc = ffma2(h2[p][k], pack2(wv, wv), acc);
        }
        h3[p][d] = acc;
    }
    __syncthreads();

    // ---- log-softmax per image ----
    if (t < 16) {
        int p = t >> 1, hf = t & 1;
        float v[10];
        #pragma unroll
        for (int d = 0; d < 10; d++) {
            float2 u = unpack2(h3[p][d]);
            v[d] = hf ? u.y : u.x;
        }
        float m = -1e30f;
        #pragma unroll
        for (int d = 0; d < 10; d++) m = fmaxf(m, v[d]);
        float s = 0.f;
        #pragma unroll
        for (int d = 0; d < 10; d++) s += __expf(v[d] - m);
        float lse = m + __logf(s);
        float* op = g_logp + (size_t)((p0 + p) * 2 + hf) * 10;
        #pragma unroll
        for (int d = 0; d < 10; d++) op[d] = v[d] - lse;
    }
}

// ---------------- probabilistic circuit: segment logsumexp over i+j=s ---------
__global__ __launch_bounds__(256) void circuit_kernel(float* __restrict__ out) {
    __shared__ float lp[40];
    __shared__ float lp1[100];
    __shared__ float lp2[100];
    int bI = blockIdx.x;
    int t = threadIdx.x;
    if (t < 40) lp[t] = g_logp[(size_t)bI * 40 + t];
    __syncthreads();
    if (t < 100) {
        lp1[t] = lp[0 + t / 10] + lp[10 + t % 10];
    } else if (t < 200) {
        int k = t - 100;
        lp2[k] = lp[20 + k / 10] + lp[30 + k % 10];
    }
    __syncthreads();
    if (t < SUMS) {
        int lo = t > 99 ? t - 99 : 0;
        int hi = t < 99 ? t : 99;
        float m = -1e30f;
        for (int i = lo; i <= hi; i++) m = fmaxf(m, lp1[i] + lp2[t - i]);
        float s = 0.f;
        for (int i = lo; i <= hi; i++) s += __expf(lp1[i] + lp2[t - i] - m);
        out[(size_t)bI * SUMS + t] = m + __logf(s);
    }
}

// ---------------- launch ----------------
extern "C" void kernel_launch(void* const* d_in, const int* in_sizes, int n_in,
                              void* d_out, int out_size) {
    const float* images = (const float*)d_in[0];
    const float* c1w    = (const float*)d_in[1];
    const float* c1b    = (const float*)d_in[2];
    const float* c2w    = (const float*)d_in[3];
    const float* c2b    = (const float*)d_in[4];
    const float* f1w    = (const float*)d_in[5];
    const float* f1b    = (const float*)d_in[6];
    const float* f2w    = (const float*)d_in[7];
    const float* f2b    = (const float*)d_in[8];
    const float* f3w    = (const float*)d_in[9];
    const float* f3b    = (const float*)d_in[10];
    float* out = (float*)d_out;

    prep_kernel<<<60, 256>>>(f1w, f2w, f3w);
    conv1_kernel<<<NPAIR / 4, 576>>>(images, c1w, c1b);
    conv2_kernel<<<NPAIR / 8, 256>>>(c2w, c2b);
    fc_kernel<<<NPAIR / FCP, 128>>>(f1b, f2b, f3b);
    circuit_kernel<<<NBATCH, 256>>>(out);
}

// round 10
// speedup vs baseline: 1.8059x; 1.0196x over previous
#include <cuda_runtime.h>
#include <cuda_bf16.h>
#include <math.h>

// ---------------- problem constants ----------------
#define N_IMG   16384           // B * 2 * NB_DIGITS
#define NPAIR   (N_IMG / 2)
#define NBATCH  4096
#define SUMS    199

typedef unsigned long long ull;

// ---------------- f32x2 packed helpers (Blackwell FFMA2 path) ----------------
__device__ __forceinline__ ull ffma2(ull a, ull b, ull c) {
    ull d;
    asm("fma.rn.f32x2 %0, %1, %2, %3;" : "=l"(d) : "l"(a), "l"(b), "l"(c));
    return d;
}
__device__ __forceinline__ ull pack2(float lo, float hi) {
    ull r;
    asm("mov.b64 %0, {%1, %2};" : "=l"(r) : "f"(lo), "f"(hi));
    return r;
}
__device__ __forceinline__ float2 unpack2(ull v) {
    float2 f;
    asm("mov.b64 {%0, %1}, %2;" : "=f"(f.x), "=f"(f.y) : "l"(v));
    return f;
}

// ---------------- device scratch ----------------
__device__ ull    g_pool1p[(size_t)NPAIR * 864];  // conv1+pool+relu, pair-packed
__device__ ull    g_pool2p[(size_t)NPAIR * 256];  // conv2+pool+relu, pair-packed NCHW
__device__ float  g_logp [(size_t)N_IMG * 10];    // per-image log-softmax
__device__ float2 g_w1v[128 * 120];               // fc1 w: [k/2][j] -> {w[k][j], w[k+1][j]}
__device__ float2 g_w2v[60 * 84];                 // fc2 w interleaved same way
__device__ float  g_w3t[84 * 10];                 // fc3 w transposed [k][j]

// ---------------- weight prep: transpose + k-pair interleave ----------------
__global__ void prep_kernel(const float* __restrict__ w1, const float* __restrict__ w2,
                            const float* __restrict__ w3) {
    int i = blockIdx.x * blockDim.x + threadIdx.x;
    if (i < 128 * 120) {
        int kk = i / 120, j = i % 120;
        g_w1v[i] = make_float2(w1[j * 256 + 2 * kk], w1[j * 256 + 2 * kk + 1]);
    }
    if (i < 60 * 84) {
        int kk = i / 84, j = i % 84;
        g_w2v[i] = make_float2(w2[j * 120 + 2 * kk], w2[j * 120 + 2 * kk + 1]);
    }
    if (i < 84 * 10) {
        int k = i / 10, j = i % 10;
        g_w3t[i] = w3[j * 84 + k];
    }
}

// ---------------- conv1 (1->6, 5x5) + maxpool2 + relu ----------------
// 4 pairs (8 images) per block, 576 threads = 4 pairs x 144 pooled positions
// image rows padded to 29 ull to reduce smem bank conflicts
__global__ __launch_bounds__(576) void conv1_kernel(const float* __restrict__ img,
                                                    const float* __restrict__ w,
                                                    const float* __restrict__ b) {
    __shared__ ull   sp[4][812];                  // 28 rows x 29 stride
    __shared__ ull   swp[150];
    __shared__ float sb[6];
    int t = threadIdx.x;
    size_t n0 = (size_t)blockIdx.x * 8;           // first image
    for (int i = t; i < 4 * 784; i += 576) {
        int q = i / 784, j = i % 784;
        int r = j / 28, c = j % 28;
        sp[q][r * 29 + c] = pack2(img[(n0 + 2 * q) * 784 + j],
                                  img[(n0 + 2 * q + 1) * 784 + j]);
    }
    if (t < 150) { float v = w[t]; swp[t] = pack2(v, v); }
    if (t < 6)   sb[t] = b[t];
    __syncthreads();

    int pairIdx = t / 144;                        // 0..3
    int pos = t % 144;
    int py = pos / 12, px = pos % 12;
    const ull* si = sp[pairIdx];

    ull acc[6][4];
    #pragma unroll
    for (int ic = 0; ic < 6; ic++)
        #pragma unroll
        for (int q = 0; q < 4; q++) acc[ic][q] = 0ULL;

    #pragma unroll
    for (int ky = 0; ky < 5; ky++) {
        #pragma unroll
        for (int kx = 0; kx < 5; kx++) {
            int base = (2 * py + ky) * 29 + 2 * px + kx;
            ull x00 = si[base],      x01 = si[base + 1];
            ull x10 = si[base + 29], x11 = si[base + 30];
            #pragma unroll
            for (int ic = 0; ic < 6; ic++) {
                ull wq = swp[ic * 25 + ky * 5 + kx];
                acc[ic][0] = ffma2(x00, wq, acc[ic][0]);
                acc[ic][1] = ffma2(x01, wq, acc[ic][1]);
                acc[ic][2] = ffma2(x10, wq, acc[ic][2]);
                acc[ic][3] = ffma2(x11, wq, acc[ic][3]);
            }
        }
    }

    size_t pg = (size_t)blockIdx.x * 4 + pairIdx;
    #pragma unroll
    for (int ic = 0; ic < 6; ic++) {
        float2 a = unpack2(acc[ic][0]), c2 = unpack2(acc[ic][1]);
        float2 d = unpack2(acc[ic][2]), e  = unpack2(acc[ic][3]);
        float bb = sb[ic];
        float oA = fmaxf(fmaxf(fmaxf(a.x, c2.x), fmaxf(d.x, e.x)) + bb, 0.f);
        float oB = fmaxf(fmaxf(fmaxf(a.y, c2.y), fmaxf(d.y, e.y)) + bb, 0.f);
        g_pool1p[pg * 864 + ic * 144 + pos] = pack2(oA, oB);
    }
}

// ---------------- conv2 (6->16, 5x5) + maxpool2 + relu ----------------
// 2 pairs (4 images) per block, 128 threads = 2 pairs x 16 oc x 4 pooled rows.
// Thread owns (pair, oc, pooled-row): 4 pooled outputs via rolling 2-row
// register window loaded with broadcast LDS.128 from padded smem (row stride 14).
// Weight smem at oc-stride 151 (odd) -> the 8 distinct oc addresses per warp hit
// 8 distinct banks (conflict-free broadcast).
#define C2_LD(buf, r) { const ulonglong2* rp = reinterpret_cast<const ulonglong2*>(xc + (r) * 14); \
    _Pragma("unroll") for (int q = 0; q < 6; q++) { ulonglong2 v = rp[q]; buf[2*q] = v.x; buf[2*q+1] = v.y; } }
#define C2_TAP(ky, LO, HI) { _Pragma("unroll") for (int kx = 0; kx < 5; kx++) { \
    ull wq = wi[(ky) * 5 + kx]; \
    _Pragma("unroll") for (int px = 0; px < 4; px++) { \
        acc[px][0] = ffma2(LO[2*px+kx],   wq, acc[px][0]); \
        acc[px][1] = ffma2(LO[2*px+kx+1], wq, acc[px][1]); \
        acc[px][2] = ffma2(HI[2*px+kx],   wq, acc[px][2]); \
        acc[px][3] = ffma2(HI[2*px+kx+1], wq, acc[px][3]); } } }

__global__ __launch_bounds__(128) void conv2_kernel(const float* __restrict__ w,
                                                    const float* __restrict__ b) {
    __shared__ __align__(16) ull sx[2 * 1008];    // per pair: 6 ic x 12 rows x 14 stride
    __shared__ ull   swp[16 * 151];               // oc stride 151
    __shared__ float sb[16];
    int t = threadIdx.x;
    size_t p0 = (size_t)blockIdx.x * 2;
    for (int i = t; i < 2 * 864; i += 128) {
        int pr = i / 864, rem = i % 864;
        int ic = rem / 144, rr = (rem % 144) / 12, c = rem % 12;
        sx[pr * 1008 + ic * 168 + rr * 14 + c] = g_pool1p[p0 * 864 + i];
    }
    for (int i = t; i < 2400; i += 128) {
        int oc = i / 150, rem = i % 150;
        float v = w[i];
        swp[oc * 151 + rem] = pack2(v, v);
    }
    if (t < 16) sb[t] = b[t];
    __syncthreads();

    int pr   = t >> 6;                // pair 0..1
    int u    = t & 63;
    int oc   = u >> 2;                // 0..15
    int prow = u & 3;                 // pooled row 0..3
    const ull* xp = sx + pr * 1008;
    const ull* wp = swp + oc * 151;

    ull acc[4][4];
    #pragma unroll
    for (int px = 0; px < 4; px++)
        #pragma unroll
        for (int q = 0; q < 4; q++) acc[px][q] = 0ULL;

    ull A[12], B[12];
    #pragma unroll 1
    for (int ic = 0; ic < 6; ic++) {
        const ull* xc = xp + ic * 168;
        const ull* wi = wp + ic * 25;
        C2_LD(A, 2 * prow); C2_LD(B, 2 * prow + 1);
        C2_TAP(0, A, B);
        C2_LD(A, 2 * prow + 2); C2_TAP(1, B, A);
        C2_LD(B, 2 * prow + 3); C2_TAP(2, A, B);
        C2_LD(A, 2 * prow + 4); C2_TAP(3, B, A);
        C2_LD(B, 2 * prow + 5); C2_TAP(4, A, B);
    }

    float bb = sb[oc];
    #pragma unroll
    for (int px = 0; px < 4; px++) {
        float2 a = unpack2(acc[px][0]), c2 = unpack2(acc[px][1]);
        float2 d = unpack2(acc[px][2]), e  = unpack2(acc[px][3]);
        float oA = fmaxf(fmaxf(fmaxf(a.x, c2.x), fmaxf(d.x, e.x)) + bb, 0.f);
        float oB = fmaxf(fmaxf(fmaxf(a.y, c2.y), fmaxf(d.y, e.y)) + bb, 0.f);
        g_pool2p[(p0 + pr) * 256 + oc * 16 + prow * 4 + px] = pack2(oA, oB);
    }
}

// ---------------- fused FC1+FC2+FC3+log_softmax ----------------
// 8 pairs (16 images) per block, 128 threads; thread j owns neuron j for 8 pairs
#define FCP 8
__global__ __launch_bounds__(128) void fc_kernel(const float* __restrict__ b1,
                                                 const float* __restrict__ b2,
                                                 const float* __restrict__ b3) {
    __shared__ __align__(16) ull xs[FCP][256];
    __shared__ __align__(16) ull h1[FCP][120];
    __shared__ __align__(16) ull h2[FCP][84];
    __shared__ ull h3[FCP][10];
    int t = threadIdx.x;
    size_t p0 = (size_t)blockIdx.x * FCP;
    for (int i = t; i < FCP * 256; i += 128)
        xs[i >> 8][i & 255] = g_pool2p[p0 * 256 + i];
    __syncthreads();

    // ---- layer 1: 256 -> 120, relu ----
    if (t < 120) {
        float bb = b1[t];
        ull bp = pack2(bb, bb);
        ull acc[FCP];
        #pragma unroll
        for (int p = 0; p < FCP; p++) acc[p] = bp;
        #pragma unroll 8
        for (int kk = 0; kk < 128; kk++) {
            float2 wv = g_w1v[kk * 120 + t];
            ull wq0 = pack2(wv.x, wv.x);
            ull wq1 = pack2(wv.y, wv.y);
            #pragma unroll
            for (int p = 0; p < FCP; p++) {
                ulonglong2 xv = *reinterpret_cast<const ulonglong2*>(&xs[p][2 * kk]);
                acc[p] = ffma2(xv.x, wq0, acc[p]);
                acc[p] = ffma2(xv.y, wq1, acc[p]);
            }
        }
        #pragma unroll
        for (int p = 0; p < FCP; p++) {
            float2 u = unpack2(acc[p]);
            h1[p][t] = pack2(fmaxf(u.x, 0.f), fmaxf(u.y, 0.f));
        }
    }
    __syncthreads();

    // ---- layer 2: 120 -> 84, relu ----
    if (t < 84) {
        float bb = b2[t];
        ull bp = pack2(bb, bb);
        ull acc[FCP];
        #pragma unroll
        for (int p = 0; p < FCP; p++) acc[p] = bp;
        #pragma unroll 6
        for (int kk = 0; kk < 60; kk++) {
            float2 wv = g_w2v[kk * 84 + t];
            ull wq0 = pack2(wv.x, wv.x);
            ull wq1 = pack2(wv.y, wv.y);
            #pragma unroll
            for (int p = 0; p < FCP; p++) {
                ulonglong2 xv = *reinterpret_cast<const ulonglong2*>(&h1[p][2 * kk]);
                acc[p] = ffma2(xv.x, wq0, acc[p]);
                acc[p] = ffma2(xv.y, wq1, acc[p]);
            }
        }
        #pragma unroll
        for (int p = 0; p < FCP; p++) {
            float2 u = unpack2(acc[p]);
            h2[p][t] = pack2(fmaxf(u.x, 0.f), fmaxf(u.y, 0.f));
        }
    }
    __syncthreads();

    // ---- layer 3: 84 -> 10 (no relu) ----
    if (t < 80) {
        int p = t / 10, d = t % 10;
        float bb = b3[d];
        ull acc = pack2(bb, bb);
        #pragma unroll 4
        for (int k = 0; k < 84; k++) {
            float wv = g_w3t[k * 10 + d];
            acc = ffma2(h2[p][k], pack2(wv, wv), acc);
        }
        h3[p][d] = acc;
    }
    __syncthreads();

    // ---- log-softmax per image ----
    if (t < 16) {
        int p = t >> 1, hf = t & 1;
        float v[10];
        #pragma unroll
        for (int d = 0; d < 10; d++) {
            float2 u = unpack2(h3[p][d]);
            v[d] = hf ? u.y : u.x;
        }
        float m = -1e30f;
        #pragma unroll
        for (int d = 0; d < 10; d++) m = fmaxf(m, v[d]);
        float s = 0.f;
        #pragma unroll
        for (int d = 0; d < 10; d++) s += __expf(v[d] - m);
        float lse = m + __logf(s);
        float* op = g_logp + (size_t)((p0 + p) * 2 + hf) * 10;
        #pragma unroll
        for (int d = 0; d < 10; d++) op[d] = v[d] - lse;
    }
}

// ---------------- probabilistic circuit: segment logsumexp over i+j=s ---------
// linear-space: out[s] = log( sum_i exp(lp1[i]) * exp(lp2[s-i]) )
// values >= e^-60 -> no underflow; analytically identical to segment logsumexp
__global__ __launch_bounds__(256) void circuit_kernel(float* __restrict__ out) {
    __shared__ float lp[40];
    __shared__ float e1[100];
    __shared__ float e2[100];
    int bI = blockIdx.x;
    int t = threadIdx.x;
    if (t < 40) lp[t] = g_logp[(size_t)bI * 40 + t];
    __syncthreads();
    if (t < 100) {
        e1[t] = __expf(lp[0 + t / 10] + lp[10 + t % 10]);
    } else if (t < 200) {
        int k = t - 100;
        e2[k] = __expf(lp[20 + k / 10] + lp[30 + k % 10]);
    }
    __syncthreads();
    if (t < SUMS) {
        int lo = t > 99 ? t - 99 : 0;
        int hi = t < 99 ? t : 99;
        float s = 0.f;
        for (int i = lo; i <= hi; i++) s = fmaf(e1[i], e2[t - i], s);
        out[(size_t)bI * SUMS + t] = __logf(s);
    }
}

// ---------------- launch ----------------
extern "C" void kernel_launch(void* const* d_in, const int* in_sizes, int n_in,
                              void* d_out, int out_size) {
    const float* images = (const float*)d_in[0];
    const float* c1w    = (const float*)d_in[1];
    const float* c1b    = (const float*)d_in[2];
    const float* c2w    = (const float*)d_in[3];
    const float* c2b    = (const float*)d_in[4];
    const float* f1w    = (const float*)d_in[5];
    const float* f1b    = (const float*)d_in[6];
    const float* f2w    = (const float*)d_in[7];
    const float* f2b    = (const float*)d_in[8];
    const float* f3w    = (const float*)d_in[9];
    const float* f3b    = (const float*)d_in[10];
    float* out = (float*)d_out;

    prep_kernel<<<60, 256>>>(f1w, f2w, f3w);
    conv1_kernel<<<NPAIR / 4, 576>>>(images, c1w, c1b);
    conv2_kernel<<<NPAIR / 2, 128>>>(c2w, c2b);
    fc_kernel<<<NPAIR / FCP, 128>>>(f1b, f2b, f3b);
    circuit_kernel<<<NBATCH, 256>>>(out);
}

// round 12
// speedup vs baseline: 1.8998x; 1.0520x over previous
#include <cuda_runtime.h>
#include <cuda_bf16.h>
#include <math.h>
#include <stdint.h>

// ---------------- problem constants ----------------
#define N_IMG   16384           // B * 2 * NB_DIGITS
#define NPAIR   (N_IMG / 2)
#define NBATCH  4096
#define SUMS    199

typedef unsigned long long ull;

// ---------------- f32x2 packed helpers (Blackwell FFMA2 path) ----------------
__device__ __forceinline__ ull ffma2(ull a, ull b, ull c) {
    ull d;
    asm("fma.rn.f32x2 %0, %1, %2, %3;" : "=l"(d) : "l"(a), "l"(b), "l"(c));
    return d;
}
__device__ __forceinline__ ull pack2(float lo, float hi) {
    ull r;
    asm("mov.b64 %0, {%1, %2};" : "=l"(r) : "f"(lo), "f"(hi));
    return r;
}
__device__ __forceinline__ float2 unpack2(ull v) {
    float2 f;
    asm("mov.b64 {%0, %1}, %2;" : "=f"(f.x), "=f"(f.y) : "l"(v));
    return f;
}

// ---------------- mma.sync helpers (bf16 HMMA, arch-portable) ----------------
#define MMA_BF16(c, a0, a1, a2, a3, b0, b1) \
    asm volatile("mma.sync.aligned.m16n8k16.row.col.f32.bf16.bf16.f32 " \
        "{%0,%1,%2,%3}, {%4,%5,%6,%7}, {%8,%9}, {%0,%1,%2,%3};" \
        : "+f"((c)[0]), "+f"((c)[1]), "+f"((c)[2]), "+f"((c)[3]) \
        : "r"(a0), "r"(a1), "r"(a2), "r"(a3), "r"(b0), "r"(b1))

__device__ __forceinline__ uint32_t pkbf(float x, float y) {
    __nv_bfloat162 v = __floats2bfloat162_rn(x, y);   // lo=x, hi=y
    return *(uint32_t*)&v;
}
__device__ __forceinline__ uint32_t pkbf16(__nv_bfloat16 lo, __nv_bfloat16 hi) {
    return ((uint32_t)__bfloat16_as_ushort(hi) << 16) | (uint32_t)__bfloat16_as_ushort(lo);
}

// ---------------- device scratch ----------------
__device__ ull    g_pool1p[(size_t)NPAIR * 864];  // conv1+pool+relu, pair-packed
__device__ ull    g_pool2p[(size_t)NPAIR * 256];  // conv2+pool+relu, pair-packed NCHW
__device__ float  g_logp [(size_t)N_IMG * 10];    // per-image log-softmax
__device__ float  g_w3t[84 * 10];                 // fc3 w transposed [k][j]
// fc weights pre-packed in mma.sync B-fragment layout (hi/lo bf16 split)
// B1: [kstep 16][ntile 16][lane 32] -> uint2 {reg0, reg1}
__device__ uint2  g_B1fh[16 * 16 * 32];
__device__ uint2  g_B1fl[16 * 16 * 32];
// B2: [kstep 8][ntile 11][lane 32]
__device__ uint2  g_B2fh[8 * 11 * 32];
__device__ uint2  g_B2fl[8 * 11 * 32];

// ---------------- weight prep: bf16 split + B-fragment packing --------------
__global__ void prep_kernel(const float* __restrict__ w1, const float* __restrict__ w2,
                            const float* __restrict__ w3) {
    int i = blockIdx.x * blockDim.x + threadIdx.x;
    if (i < 8192) {                       // B1 frags: 16 ks x 16 nt x 32 lanes
        int lane = i & 31, nt = (i >> 5) & 15, ks = i >> 9;
        int n = nt * 8 + (lane >> 2);
        int k0 = ks * 16 + (lane & 3) * 2;
        float e[4];
        #pragma unroll
        for (int q = 0; q < 4; q++) {
            int k = k0 + (q >> 1) * 8 + (q & 1);
            e[q] = (n < 120) ? w1[n * 256 + k] : 0.f;
        }
        __nv_bfloat16 h[4]; float l[4];
        #pragma unroll
        for (int q = 0; q < 4; q++) { h[q] = __float2bfloat16(e[q]); l[q] = e[q] - __bfloat162float(h[q]); }
        g_B1fh[i] = make_uint2(pkbf16(h[0], h[1]), pkbf16(h[2], h[3]));
        g_B1fl[i] = make_uint2(pkbf(l[0], l[1]), pkbf(l[2], l[3]));
    } else if (i < 8192 + 2816) {         // B2 frags: 8 ks x 11 nt x 32 lanes
        int r = i - 8192;
        int lane = r & 31, nt = (r >> 5) % 11, ks = r / 352;
        int n = nt * 8 + (lane >> 2);
        int k0 = ks * 16 + (lane & 3) * 2;
        float e[4];
        #pragma unroll
        for (int q = 0; q < 4; q++) {
            int k = k0 + (q >> 1) * 8 + (q & 1);
            e[q] = (n < 84 && k < 120) ? w2[n * 120 + k] : 0.f;
        }
        __nv_bfloat16 h[4]; float l[4];
        #pragma unroll
        for (int q = 0; q < 4; q++) { h[q] = __float2bfloat16(e[q]); l[q] = e[q] - __bfloat162float(h[q]); }
        g_B2fh[r] = make_uint2(pkbf16(h[0], h[1]), pkbf16(h[2], h[3]));
        g_B2fl[r] = make_uint2(pkbf(l[0], l[1]), pkbf(l[2], l[3]));
    }
    if (i < 840) { int k = i / 10, j = i % 10; g_w3t[i] = w3[j * 84 + k]; }
}

// ---------------- conv1 (1->6, 5x5) + maxpool2 + relu (R10) ------------------
__global__ __launch_bounds__(576) void conv1_kernel(const float* __restrict__ img,
                                                    const float* __restrict__ w,
                                                    const float* __restrict__ b) {
    __shared__ ull   sp[4][812];
    __shared__ ull   swp[150];
    __shared__ float sb[6];
    int t = threadIdx.x;
    size_t n0 = (size_t)blockIdx.x * 8;
    for (int i = t; i < 4 * 784; i += 576) {
        int q = i / 784, j = i % 784;
        int r = j / 28, c = j % 28;
        sp[q][r * 29 + c] = pack2(img[(n0 + 2 * q) * 784 + j],
                                  img[(n0 + 2 * q + 1) * 784 + j]);
    }
    if (t < 150) { float v = w[t]; swp[t] = pack2(v, v); }
    if (t < 6)   sb[t] = b[t];
    __syncthreads();

    int pairIdx = t / 144;
    int pos = t % 144;
    int py = pos / 12, px = pos % 12;
    const ull* si = sp[pairIdx];

    ull acc[6][4];
    #pragma unroll
    for (int ic = 0; ic < 6; ic++)
        #pragma unroll
        for (int q = 0; q < 4; q++) acc[ic][q] = 0ULL;

    #pragma unroll
    for (int ky = 0; ky < 5; ky++) {
        #pragma unroll
        for (int kx = 0; kx < 5; kx++) {
            int base = (2 * py + ky) * 29 + 2 * px + kx;
            ull x00 = si[base],      x01 = si[base + 1];
            ull x10 = si[base + 29], x11 = si[base + 30];
            #pragma unroll
            for (int ic = 0; ic < 6; ic++) {
                ull wq = swp[ic * 25 + ky * 5 + kx];
                acc[ic][0] = ffma2(x00, wq, acc[ic][0]);
                acc[ic][1] = ffma2(x01, wq, acc[ic][1]);
                acc[ic][2] = ffma2(x10, wq, acc[ic][2]);
                acc[ic][3] = ffma2(x11, wq, acc[ic][3]);
            }
        }
    }

    size_t pg = (size_t)blockIdx.x * 4 + pairIdx;
    #pragma unroll
    for (int ic = 0; ic < 6; ic++) {
        float2 a = unpack2(acc[ic][0]), c2 = unpack2(acc[ic][1]);
        float2 d = unpack2(acc[ic][2]), e  = unpack2(acc[ic][3]);
        float bb = sb[ic];
        float oA = fmaxf(fmaxf(fmaxf(a.x, c2.x), fmaxf(d.x, e.x)) + bb, 0.f);
        float oB = fmaxf(fmaxf(fmaxf(a.y, c2.y), fmaxf(d.y, e.y)) + bb, 0.f);
        g_pool1p[pg * 864 + ic * 144 + pos] = pack2(oA, oB);
    }
}

// ---------------- conv2 (6->16, 5x5) + maxpool2 + relu (R10) -----------------
#define C2_LD(buf, r) { const ulonglong2* rp = reinterpret_cast<const ulonglong2*>(xc + (r) * 14); \
    _Pragma("unroll") for (int q = 0; q < 6; q++) { ulonglong2 v = rp[q]; buf[2*q] = v.x; buf[2*q+1] = v.y; } }
#define C2_TAP(ky, LO, HI) { _Pragma("unroll") for (int kx = 0; kx < 5; kx++) { \
    ull wq = wi[(ky) * 5 + kx]; \
    _Pragma("unroll") for (int px = 0; px < 4; px++) { \
        acc[px][0] = ffma2(LO[2*px+kx],   wq, acc[px][0]); \
        acc[px][1] = ffma2(LO[2*px+kx+1], wq, acc[px][1]); \
        acc[px][2] = ffma2(HI[2*px+kx],   wq, acc[px][2]); \
        acc[px][3] = ffma2(HI[2*px+kx+1], wq, acc[px][3]); } } }

__global__ __launch_bounds__(128) void conv2_kernel(const float* __restrict__ w,
                                                    const float* __restrict__ b) {
    __shared__ __align__(16) ull sx[2 * 1008];
    __shared__ ull   swp[16 * 151];
    __shared__ float sb[16];
    int t = threadIdx.x;
    size_t p0 = (size_t)blockIdx.x * 2;
    for (int i = t; i < 2 * 864; i += 128) {
        int pr = i / 864, rem = i % 864;
        int ic = rem / 144, rr = (rem % 144) / 12, c = rem % 12;
        sx[pr * 1008 + ic * 168 + rr * 14 + c] = g_pool1p[p0 * 864 + i];
    }
    for (int i = t; i < 2400; i += 128) {
        int oc = i / 150, rem = i % 150;
        float v = w[i];
        swp[oc * 151 + rem] = pack2(v, v);
    }
    if (t < 16) sb[t] = b[t];
    __syncthreads();

    int pr   = t >> 6;
    int u    = t & 63;
    int oc   = u >> 2;
    int prow = u & 3;
    const ull* xp = sx + pr * 1008;
    const ull* wp = swp + oc * 151;

    ull acc[4][4];
    #pragma unroll
    for (int px = 0; px < 4; px++)
        #pragma unroll
        for (int q = 0; q < 4; q++) acc[px][q] = 0ULL;

    ull A[12], B[12];
    #pragma unroll 1
    for (int ic = 0; ic < 6; ic++) {
        const ull* xc = xp + ic * 168;
        const ull* wi = wp + ic * 25;
        C2_LD(A, 2 * prow); C2_LD(B, 2 * prow + 1);
        C2_TAP(0, A, B);
        C2_LD(A, 2 * prow + 2); C2_TAP(1, B, A);
        C2_LD(B, 2 * prow + 3); C2_TAP(2, A, B);
        C2_LD(A, 2 * prow + 4); C2_TAP(3, B, A);
        C2_LD(B, 2 * prow + 5); C2_TAP(4, A, B);
    }

    float bb = sb[oc];
    #pragma unroll
    for (int px = 0; px < 4; px++) {
        float2 a = unpack2(acc[px][0]), c2 = unpack2(acc[px][1]);
        float2 d = unpack2(acc[px][2]), e  = unpack2(acc[px][3]);
        float oA = fmaxf(fmaxf(fmaxf(a.x, c2.x), fmaxf(d.x, e.x)) + bb, 0.f);
        float oB = fmaxf(fmaxf(fmaxf(a.y, c2.y), fmaxf(d.y, e.y)) + bb, 0.f);
        g_pool2p[(p0 + pr) * 256 + oc * 16 + prow * 4 + px] = pack2(oA, oB);
    }
}

// ---------------- fc chain on mma.sync (HMMA bf16, 3-term split) -------------
// CTA = 128 images, 256 threads (8 warps); warp w owns M-tile rows w*16..w*16+15.
#define SAW 264                 // A smem row stride in bf16 elems (conflict-free)
#define A_HI 0
#define A_LO 67584
#define SH2  135168             // h2 fp32 [128][90]
#define SB1  181248
#define SB2  181760
#define SB3  182144
#define SW3  182208
#define S_TOTAL 185600

__global__ __launch_bounds__(256, 1)
void fc_mma_kernel(const float* __restrict__ b1, const float* __restrict__ b2,
                   const float* __restrict__ b3) {
    extern __shared__ __align__(16) char sm[];
    int t = threadIdx.x, wid = t >> 5, lane = t & 31;
    float* sb1 = (float*)(sm + SB1);
    float* sb2 = (float*)(sm + SB2);
    float* sb3 = (float*)(sm + SB3);
    float* sw3 = (float*)(sm + SW3);
    float* sh2 = (float*)(sm + SH2);

    if (t < 120) sb1[t] = b1[t];
    if (t < 84)  sb2[t] = b2[t];
    if (t < 10)  sb3[t] = b3[t];
    for (int i = t; i < 840; i += 256) sw3[i] = g_w3t[i];

    // ---- stage A1: fp32 -> bf16 hi/lo, row-major stride SAW ----
    {
        int r = t >> 1, kh = t & 1;
        size_t img = (size_t)blockIdx.x * 128 + r;
        size_t pg = img >> 1;
        int half = (int)(img & 1);
        const ull* xp = g_pool2p + pg * 256 + kh * 128;
        #pragma unroll 4
        for (int u = 0; u < 64; u++) {
            int k = kh * 128 + 2 * u;
            float2 f0 = unpack2(xp[2 * u]);
            float2 f1 = unpack2(xp[2 * u + 1]);
            float x0 = half ? f0.y : f0.x;
            float x1 = half ? f1.y : f1.x;
            __nv_bfloat16 h0 = __float2bfloat16(x0), h1 = __float2bfloat16(x1);
            float l0 = x0 - __bfloat162float(h0);
            float l1 = x1 - __bfloat162float(h1);
            *(uint32_t*)(sm + A_HI + ((size_t)r * SAW + k) * 2) = pkbf16(h0, h1);
            *(uint32_t*)(sm + A_LO + ((size_t)r * SAW + k) * 2) = pkbf(l0, l1);
        }
    }
    __syncthreads();

    // ---- fc1: [128x256] x [256x128] -> acc[16 ntiles][4] ----
    int r0 = wid * 16;
    int ar = r0 + (lane >> 2);
    float acc[16][4];
    #pragma unroll
    for (int nt = 0; nt < 16; nt++)
        #pragma unroll
        for (int q = 0; q < 4; q++) acc[nt][q] = 0.f;

    #pragma unroll 1
    for (int ks = 0; ks < 16; ks++) {
        int ac = ks * 16 + (lane & 3) * 2;
        uint32_t ah0 = *(uint32_t*)(sm + A_HI + ((size_t)ar * SAW + ac) * 2);
        uint32_t ah1 = *(uint32_t*)(sm + A_HI + ((size_t)(ar + 8) * SAW + ac) * 2);
        uint32_t ah2 = *(uint32_t*)(sm + A_HI + ((size_t)ar * SAW + ac + 8) * 2);
        uint32_t ah3 = *(uint32_t*)(sm + A_HI + ((size_t)(ar + 8) * SAW + ac + 8) * 2);
        uint32_t al0 = *(uint32_t*)(sm + A_LO + ((size_t)ar * SAW + ac) * 2);
        uint32_t al1 = *(uint32_t*)(sm + A_LO + ((size_t)(ar + 8) * SAW + ac) * 2);
        uint32_t al2 = *(uint32_t*)(sm + A_LO + ((size_t)ar * SAW + ac + 8) * 2);
        uint32_t al3 = *(uint32_t*)(sm + A_LO + ((size_t)(ar + 8) * SAW + ac + 8) * 2);
        #pragma unroll
        for (int nt = 0; nt < 16; nt++) {
            uint2 bh = g_B1fh[ks * 512 + nt * 32 + lane];
            uint2 bl = g_B1fl[ks * 512 + nt * 32 + lane];
            MMA_BF16(acc[nt], ah0, ah1, ah2, ah3, bh.x, bh.y);
            MMA_BF16(acc[nt], ah0, ah1, ah2, ah3, bl.x, bl.y);
            MMA_BF16(acc[nt], al0, al1, al2, al3, bh.x, bh.y);
        }
    }

    // ---- bias + relu -> A2 fragments (in registers, no smem round trip) ----
    uint32_t a2h[8][4], a2l[8][4];
    #pragma unroll
    for (int k2 = 0; k2 < 8; k2++) {
        #pragma unroll
        for (int e = 0; e < 2; e++) {
            int nt = 2 * k2 + e;
            int j0 = nt * 8 + (lane & 3) * 2;
            float bb0 = (j0 < 120)     ? sb1[j0]     : 0.f;
            float bb1 = (j0 + 1 < 120) ? sb1[j0 + 1] : 0.f;
            float v0 = fmaxf(acc[nt][0] + bb0, 0.f);
            float v1 = fmaxf(acc[nt][1] + bb1, 0.f);
            float v2 = fmaxf(acc[nt][2] + bb0, 0.f);
            float v3 = fmaxf(acc[nt][3] + bb1, 0.f);
            __nv_bfloat16 h0 = __float2bfloat16(v0), h1 = __float2bfloat16(v1);
            __nv_bfloat16 h2 = __float2bfloat16(v2), h3 = __float2bfloat16(v3);
            a2h[k2][0 + 2 * e] = pkbf16(h0, h1);
            a2h[k2][1 + 2 * e] = pkbf16(h2, h3);
            a2l[k2][0 + 2 * e] = pkbf(v0 - __bfloat162float(h0), v1 - __bfloat162float(h1));
            a2l[k2][1 + 2 * e] = pkbf(v2 - __bfloat162float(h2), v3 - __bfloat162float(h3));
        }
    }

    // ---- fc2: [128x128] x [128x88] -> acc2[11][4] ----
    float acc2[11][4];
    #pragma unroll
    for (int nt = 0; nt < 11; nt++)
        #pragma unroll
        for (int q = 0; q < 4; q++) acc2[nt][q] = 0.f;
    #pragma unroll 1
    for (int ks = 0; ks < 8; ks++) {
        #pragma unroll
        for (int nt = 0; nt < 11; nt++) {
            uint2 bh = g_B2fh[ks * 352 + nt * 32 + lane];
            uint2 bl = g_B2fl[ks * 352 + nt * 32 + lane];
            MMA_BF16(acc2[nt], a2h[ks][0], a2h[ks][1], a2h[ks][2], a2h[ks][3], bh.x, bh.y);
            MMA_BF16(acc2[nt], a2h[ks][0], a2h[ks][1], a2h[ks][2], a2h[ks][3], bl.x, bl.y);
            MMA_BF16(acc2[nt], a2l[ks][0], a2l[ks][1], a2l[ks][2], a2l[ks][3], bh.x, bh.y);
        }
    }

    // ---- bias + relu -> h2 fp32 in smem ----
    {
        int rr = r0 + (lane >> 2);
        #pragma unroll
        for (int nt = 0; nt < 11; nt++) {
            int j0 = nt * 8 + (lane & 3) * 2;
            float bb0 = (j0 < 84)     ? sb2[j0]     : 0.f;
            float bb1 = (j0 + 1 < 84) ? sb2[j0 + 1] : 0.f;
            *(float2*)(sh2 + (size_t)rr * 90 + j0) =
                make_float2(fmaxf(acc2[nt][0] + bb0, 0.f), fmaxf(acc2[nt][1] + bb1, 0.f));
            *(float2*)(sh2 + (size_t)(rr + 8) * 90 + j0) =
                make_float2(fmaxf(acc2[nt][2] + bb0, 0.f), fmaxf(acc2[nt][3] + bb1, 0.f));
        }
    }
    __syncthreads();

    // ---- fc3 + log-softmax (threads 0..127, one row each) ----
    if (t < 128) {
        const float* hp = sh2 + (size_t)t * 90;
        float o[10];
        #pragma unroll
        for (int j = 0; j < 10; j++) o[j] = sb3[j];
        #pragma unroll 4
        for (int k = 0; k < 84; k++) {
            float hv = hp[k];
            #pragma unroll
            for (int j = 0; j < 10; j++) o[j] = fmaf(hv, sw3[k * 10 + j], o[j]);
        }
        float m = -1e30f;
        #pragma unroll
        for (int j = 0; j < 10; j++) m = fmaxf(m, o[j]);
        float s = 0.f;
        #pragma unroll
        for (int j = 0; j < 10; j++) s += __expf(o[j] - m);
        float lse = m + __logf(s);
        float* op = g_logp + ((size_t)blockIdx.x * 128 + t) * 10;
        #pragma unroll
        for (int j = 0; j < 10; j++) op[j] = o[j] - lse;
    }
}

// ---------------- probabilistic circuit (R10) ----------------
__global__ __launch_bounds__(256) void circuit_kernel(float* __restrict__ out) {
    __shared__ float lp[40];
    __shared__ float e1[100];
    __shared__ float e2[100];
    int bI = blockIdx.x;
    int t = threadIdx.x;
    if (t < 40) lp[t] = g_logp[(size_t)bI * 40 + t];
    __syncthreads();
    if (t < 100) {
        e1[t] = __expf(lp[0 + t / 10] + lp[10 + t % 10]);
    } else if (t < 200) {
        int k = t - 100;
        e2[k] = __expf(lp[20 + k / 10] + lp[30 + k % 10]);
    }
    __syncthreads();
    if (t < SUMS) {
        int lo = t > 99 ? t - 99 : 0;
        int hi = t < 99 ? t : 99;
        float s = 0.f;
        for (int i = lo; i <= hi; i++) s = fmaf(e1[i], e2[t - i], s);
        out[(size_t)bI * SUMS + t] = __logf(s);
    }
}

// ---------------- launch ----------------
extern "C" void kernel_launch(void* const* d_in, const int* in_sizes, int n_in,
                              void* d_out, int out_size) {
    const float* images = (const float*)d_in[0];
    const float* c1w    = (const float*)d_in[1];
    const float* c1b    = (const float*)d_in[2];
    const float* c2w    = (const float*)d_in[3];
    const float* c2b    = (const float*)d_in[4];
    const float* f1w    = (const float*)d_in[5];
    const float* f1b    = (const float*)d_in[6];
    const float* f2w    = (const float*)d_in[7];
    const float* f2b    = (const float*)d_in[8];
    const float* f3w    = (const float*)d_in[9];
    const float* f3b    = (const float*)d_in[10];
    float* out = (float*)d_out;

    cudaFuncSetAttribute(fc_mma_kernel, cudaFuncAttributeMaxDynamicSharedMemorySize, S_TOTAL);

    prep_kernel<<<44, 256>>>(f1w, f2w, f3w);
    conv1_kernel<<<NPAIR / 4, 576>>>(images, c1w, c1b);
    conv2_kernel<<<NPAIR / 2, 128>>>(c2w, c2b);
    fc_mma_kernel<<<N_IMG / 128, 256, S_TOTAL>>>(f1b, f2b, f3b);
    circuit_kernel<<<NBATCH, 256>>>(out);
}

// round 13
// speedup vs baseline: 2.2003x; 1.1582x over previous
#include <cuda_runtime.h>
#include <cuda_bf16.h>
#include <math.h>
#include <stdint.h>

// ---------------- problem constants ----------------
#define N_IMG   16384           // B * 2 * NB_DIGITS
#define NPAIR   (N_IMG / 2)
#define NBATCH  4096
#define SUMS    199

typedef unsigned long long ull;

// ---------------- f32x2 packed helpers ----------------
__device__ __forceinline__ ull ffma2(ull a, ull b, ull c) {
    ull d;
    asm("fma.rn.f32x2 %0, %1, %2, %3;" : "=l"(d) : "l"(a), "l"(b), "l"(c));
    return d;
}
__device__ __forceinline__ ull pack2(float lo, float hi) {
    ull r;
    asm("mov.b64 %0, {%1, %2};" : "=l"(r) : "f"(lo), "f"(hi));
    return r;
}
__device__ __forceinline__ float2 unpack2(ull v) {
    float2 f;
    asm("mov.b64 {%0, %1}, %2;" : "=f"(f.x), "=f"(f.y) : "l"(v));
    return f;
}

// ---------------- mma.sync helpers (bf16 HMMA) ----------------
#define MMA_BF16(c, a0, a1, a2, a3, b0, b1) \
    asm volatile("mma.sync.aligned.m16n8k16.row.col.f32.bf16.bf16.f32 " \
        "{%0,%1,%2,%3}, {%4,%5,%6,%7}, {%8,%9}, {%0,%1,%2,%3};" \
        : "+f"((c)[0]), "+f"((c)[1]), "+f"((c)[2]), "+f"((c)[3]) \
        : "r"(a0), "r"(a1), "r"(a2), "r"(a3), "r"(b0), "r"(b1))

__device__ __forceinline__ uint32_t pkbf(float x, float y) {
    __nv_bfloat162 v = __floats2bfloat162_rn(x, y);   // lo=x, hi=y
    return *(uint32_t*)&v;
}
__device__ __forceinline__ uint32_t pkbf16(__nv_bfloat16 lo, __nv_bfloat16 hi) {
    return ((uint32_t)__bfloat16_as_ushort(hi) << 16) | (uint32_t)__bfloat16_as_ushort(lo);
}

// ---------------- device scratch ----------------
__device__ ull    g_pool1p[(size_t)NPAIR * 864];  // conv1+pool+relu, pair-packed
__device__ float  g_pool2f[(size_t)N_IMG * 256];  // conv2+pool+relu, per-image NCHW
__device__ float  g_logp [(size_t)N_IMG * 10];    // per-image log-softmax
__device__ float  g_w3t[84 * 10];                 // fc3 w transposed [k][j]
// fc weights in mma B-fragment layout (hi/lo bf16 split)
__device__ uint2  g_B1fh[16 * 16 * 32];
__device__ uint2  g_B1fl[16 * 16 * 32];
__device__ uint2  g_B2fh[8 * 11 * 32];
__device__ uint2  g_B2fl[8 * 11 * 32];
// conv2 weights in mma A-fragment layout: [ks 10][lane 32], hi/lo
__device__ uint4  g_CAh[10 * 32];
__device__ uint4  g_CAl[10 * 32];

// ---------------- weight prep ----------------
__global__ void prep_kernel(const float* __restrict__ c2w,
                            const float* __restrict__ w1, const float* __restrict__ w2,
                            const float* __restrict__ w3) {
    int i = blockIdx.x * blockDim.x + threadIdx.x;
    if (i < 8192) {                       // B1 frags: 16 ks x 16 nt x 32 lanes
        int lane = i & 31, nt = (i >> 5) & 15, ks = i >> 9;
        int n = nt * 8 + (lane >> 2);
        int k0 = ks * 16 + (lane & 3) * 2;
        float e[4];
        #pragma unroll
        for (int q = 0; q < 4; q++) {
            int k = k0 + (q >> 1) * 8 + (q & 1);
            e[q] = (n < 120) ? w1[n * 256 + k] : 0.f;
        }
        __nv_bfloat16 h[4]; float l[4];
        #pragma unroll
        for (int q = 0; q < 4; q++) { h[q] = __float2bfloat16(e[q]); l[q] = e[q] - __bfloat162float(h[q]); }
        g_B1fh[i] = make_uint2(pkbf16(h[0], h[1]), pkbf16(h[2], h[3]));
        g_B1fl[i] = make_uint2(pkbf(l[0], l[1]), pkbf(l[2], l[3]));
    } else if (i < 8192 + 2816) {         // B2 frags: 8 ks x 11 nt x 32 lanes
        int r = i - 8192;
        int lane = r & 31, nt = (r >> 5) % 11, ks = r / 352;
        int n = nt * 8 + (lane >> 2);
        int k0 = ks * 16 + (lane & 3) * 2;
        float e[4];
        #pragma unroll
        for (int q = 0; q < 4; q++) {
            int k = k0 + (q >> 1) * 8 + (q & 1);
            e[q] = (n < 84 && k < 120) ? w2[n * 120 + k] : 0.f;
        }
        __nv_bfloat16 h[4]; float l[4];
        #pragma unroll
        for (int q = 0; q < 4; q++) { h[q] = __float2bfloat16(e[q]); l[q] = e[q] - __bfloat162float(h[q]); }
        g_B2fh[r] = make_uint2(pkbf16(h[0], h[1]), pkbf16(h[2], h[3]));
        g_B2fl[r] = make_uint2(pkbf(l[0], l[1]), pkbf(l[2], l[3]));
    }
    if (i < 320) {                        // conv2 A frags: 10 ks x 32 lanes
        int lane = i & 31, ks = i >> 5;
        int g2 = lane >> 2, tg = lane & 3;
        int k0 = ks * 16 + tg * 2;
        float e[8];
        #pragma unroll
        for (int q = 0; q < 8; q++) {
            int row = g2 + ((q >> 1) & 1) * 8;         // a0:g a1:g+8 a2:g a3:g+8
            int k = k0 + (q & 1) + (q >> 2) * 8;       // pairs at k0 and k0+8
            e[q] = (k < 150) ? c2w[row * 150 + k] : 0.f;
        }
        __nv_bfloat16 h[8]; float l[8];
        #pragma unroll
        for (int q = 0; q < 8; q++) { h[q] = __float2bfloat16(e[q]); l[q] = e[q] - __bfloat162float(h[q]); }
        g_CAh[i] = make_uint4(pkbf16(h[0], h[1]), pkbf16(h[2], h[3]),
                              pkbf16(h[4], h[5]), pkbf16(h[6], h[7]));
        g_CAl[i] = make_uint4(pkbf(l[0], l[1]), pkbf(l[2], l[3]),
                              pkbf(l[4], l[5]), pkbf(l[6], l[7]));
    }
    if (i < 840) { int k = i / 10, j = i % 10; g_w3t[i] = w3[j * 84 + k]; }
}

// ---------------- conv1 (1->6, 5x5) + maxpool2 + relu (R10, FFMA2) -----------
__global__ __launch_bounds__(576) void conv1_kernel(const float* __restrict__ img,
                                                    const float* __restrict__ w,
                                                    const float* __restrict__ b) {
    __shared__ ull   sp[4][812];
    __shared__ ull   swp[150];
    __shared__ float sb[6];
    int t = threadIdx.x;
    size_t n0 = (size_t)blockIdx.x * 8;
    for (int i = t; i < 4 * 784; i += 576) {
        int q = i / 784, j = i % 784;
        int r = j / 28, c = j % 28;
        sp[q][r * 29 + c] = pack2(img[(n0 + 2 * q) * 784 + j],
                                  img[(n0 + 2 * q + 1) * 784 + j]);
    }
    if (t < 150) { float v = w[t]; swp[t] = pack2(v, v); }
    if (t < 6)   sb[t] = b[t];
    __syncthreads();

    int pairIdx = t / 144;
    int pos = t % 144;
    int py = pos / 12, px = pos % 12;
    const ull* si = sp[pairIdx];

    ull acc[6][4];
    #pragma unroll
    for (int ic = 0; ic < 6; ic++)
        #pragma unroll
        for (int q = 0; q < 4; q++) acc[ic][q] = 0ULL;

    #pragma unroll
    for (int ky = 0; ky < 5; ky++) {
        #pragma unroll
        for (int kx = 0; kx < 5; kx++) {
            int base = (2 * py + ky) * 29 + 2 * px + kx;
            ull x00 = si[base],      x01 = si[base + 1];
            ull x10 = si[base + 29], x11 = si[base + 30];
            #pragma unroll
            for (int ic = 0; ic < 6; ic++) {
                ull wq = swp[ic * 25 + ky * 5 + kx];
                acc[ic][0] = ffma2(x00, wq, acc[ic][0]);
                acc[ic][1] = ffma2(x01, wq, acc[ic][1]);
                acc[ic][2] = ffma2(x10, wq, acc[ic][2]);
                acc[ic][3] = ffma2(x11, wq, acc[ic][3]);
            }
        }
    }

    size_t pg = (size_t)blockIdx.x * 4 + pairIdx;
    #pragma unroll
    for (int ic = 0; ic < 6; ic++) {
        float2 a = unpack2(acc[ic][0]), c2 = unpack2(acc[ic][1]);
        float2 d = unpack2(acc[ic][2]), e  = unpack2(acc[ic][3]);
        float bb = sb[ic];
        float oA = fmaxf(fmaxf(fmaxf(a.x, c2.x), fmaxf(d.x, e.x)) + bb, 0.f);
        float oB = fmaxf(fmaxf(fmaxf(a.y, c2.y), fmaxf(d.y, e.y)) + bb, 0.f);
        g_pool1p[pg * 864 + ic * 144 + pos] = pack2(oA, oB);
    }
}

// ---------------- conv2 via implicit-im2col mma.sync -------------------------
// CTA = 8 images (256 threads, 8 warps); warp = 1 image.
// GEMM per image: D[16 oc][64 pos] = W[16][160] x B[160][64], 3-term bf16 split.
// n-tile nt == conv output row oy; pooling is thread-local on D fragments.
#define CSTRIDE 872
#define CLO     6984            // lo-plane offset (ushort idx) = 8*872 + 8
#define ZIDX    6976u           // zero slot for padded K
__global__ __launch_bounds__(256) void conv2_mma_kernel(const float* __restrict__ b) {
    __shared__ unsigned short sa[2 * CLO];          // hi plane + lo plane
    __shared__ uint4 swf[2][10][32];                // A frags [hi/lo][ks][lane]
    __shared__ float sb[16];
    int t = threadIdx.x, wid = t >> 5, lane = t & 31;
    size_t p0 = (size_t)blockIdx.x * 4;             // 4 pairs = 8 images

    for (int i = t; i < 4 * 864; i += 256) {
        int pr = i / 864, j = i % 864;
        float2 f = unpack2(g_pool1p[p0 * 864 + i]);
        __nv_bfloat16 hA = __float2bfloat16(f.x);
        __nv_bfloat16 hB = __float2bfloat16(f.y);
        float lA = f.x - __bfloat162float(hA);
        float lB = f.y - __bfloat162float(hB);
        int iA = (2 * pr) * CSTRIDE + j;
        int iB = iA + CSTRIDE;
        sa[iA] = __bfloat16_as_ushort(hA);
        sa[iA + CLO] = __bfloat16_as_ushort(__float2bfloat16(lA));
        sa[iB] = __bfloat16_as_ushort(hB);
        sa[iB + CLO] = __bfloat16_as_ushort(__float2bfloat16(lB));
    }
    if (t < 8) { sa[ZIDX + t] = 0; sa[ZIDX + t + CLO] = 0; }
    for (int i = t; i < 640; i += 256)
        ((uint4*)swf)[i] = (i < 320) ? g_CAh[i] : g_CAl[i - 320];
    if (t < 16) sb[t] = b[t];
    __syncthreads();

    int g2 = lane >> 2, tg = lane & 3;
    unsigned pbase = (unsigned)(wid * CSTRIDE);

    float acc[8][4];
    #pragma unroll
    for (int nt = 0; nt < 8; nt++)
        #pragma unroll
        for (int q = 0; q < 4; q++) acc[nt][q] = 0.f;

    #pragma unroll 1
    for (int ks = 0; ks < 10; ks++) {
        uint4 ah = swf[0][ks][lane];
        uint4 al = swf[1][ks][lane];
        int k0 = ks * 16 + tg * 2;
        unsigned ko[4]; bool kv[4];
        #pragma unroll
        for (int j = 0; j < 4; j++) {
            int k = k0 + (j & 1) + (j >> 1) * 8;    // k0, k0+1, k0+8, k0+9
            kv[j] = (k < 150);
            int ic = k / 25, rr = k % 25;
            ko[j] = (unsigned)(ic * 144 + (rr / 5) * 12 + (rr % 5));
        }
        #pragma unroll
        for (int nt = 0; nt < 8; nt++) {
            unsigned base = pbase + (unsigned)(nt * 12 + g2);
            unsigned i0 = kv[0] ? base + ko[0] : ZIDX;
            unsigned i1 = kv[1] ? base + ko[1] : ZIDX;
            unsigned i2 = kv[2] ? base + ko[2] : ZIDX;
            unsigned i3 = kv[3] ? base + ko[3] : ZIDX;
            uint32_t e0 = sa[i0], e1 = sa[i1], e2 = sa[i2], e3 = sa[i3];
            uint32_t f0 = sa[i0 + CLO], f1 = sa[i1 + CLO], f2 = sa[i2 + CLO], f3 = sa[i3 + CLO];
            uint32_t bh0 = (e1 << 16) | e0, bh1 = (e3 << 16) | e2;
            uint32_t bl0 = (f1 << 16) | f0, bl1 = (f3 << 16) | f2;
            MMA_BF16(acc[nt], ah.x, ah.y, ah.z, ah.w, bh0, bh1);
            MMA_BF16(acc[nt], ah.x, ah.y, ah.z, ah.w, bl0, bl1);
            MMA_BF16(acc[nt], al.x, al.y, al.z, al.w, bh0, bh1);
        }
    }

    // thread holds conv[oc=g2][oy=nt][ox=tg*2,tg*2+1] (c0,c1) and oc=g2+8 (c2,c3)
    size_t img = (size_t)blockIdx.x * 8 + wid;
    float* op = g_pool2f + img * 256;
    float b0 = sb[g2], b1 = sb[g2 + 8];
    #pragma unroll
    for (int py = 0; py < 4; py++) {
        float m0 = fmaxf(fmaxf(acc[2 * py][0], acc[2 * py][1]),
                         fmaxf(acc[2 * py + 1][0], acc[2 * py + 1][1]));
        float m1 = fmaxf(fmaxf(acc[2 * py][2], acc[2 * py][3]),
                         fmaxf(acc[2 * py + 1][2], acc[2 * py + 1][3]));
        op[g2 * 16 + py * 4 + tg]       = fmaxf(m0 + b0, 0.f);
        op[(g2 + 8) * 16 + py * 4 + tg] = fmaxf(m1 + b1, 0.f);
    }
}

// ---------------- fc chain on mma.sync (64 rows/CTA, 128 threads) ------------
#define SAW 264
#define A_HI 0
#define A_LO 33792
#define SH2  67584
#define SB1  90624
#define SB2  91136
#define SB3  91520
#define SW3  91584
#define S_TOTAL 95232

__global__ __launch_bounds__(128, 1)
void fc_mma_kernel(const float* __restrict__ b1, const float* __restrict__ b2,
                   const float* __restrict__ b3) {
    extern __shared__ __align__(16) char sm[];
    int t = threadIdx.x, wid = t >> 5, lane = t & 31;
    float* sb1 = (float*)(sm + SB1);
    float* sb2 = (float*)(sm + SB2);
    float* sb3 = (float*)(sm + SB3);
    float* sw3 = (float*)(sm + SW3);
    float* sh2 = (float*)(sm + SH2);

    if (t < 120) sb1[t] = b1[t];
    if (t < 84)  sb2[t] = b2[t];
    if (t < 10)  sb3[t] = b3[t];
    for (int i = t; i < 840; i += 128) sw3[i] = g_w3t[i];

    // ---- stage A1: fp32 -> bf16 hi/lo ----
    {
        int r = t >> 1, kh = t & 1;
        size_t img = (size_t)blockIdx.x * 64 + r;
        const float* xp = g_pool2f + img * 256 + kh * 128;
        #pragma unroll 4
        for (int u = 0; u < 64; u++) {
            int k = kh * 128 + 2 * u;
            float x0 = xp[2 * u], x1 = xp[2 * u + 1];
            __nv_bfloat16 h0 = __float2bfloat16(x0), h1 = __float2bfloat16(x1);
            float l0 = x0 - __bfloat162float(h0);
            float l1 = x1 - __bfloat162float(h1);
            *(uint32_t*)(sm + A_HI + ((size_t)r * SAW + k) * 2) = pkbf16(h0, h1);
            *(uint32_t*)(sm + A_LO + ((size_t)r * SAW + k) * 2) = pkbf(l0, l1);
        }
    }
    __syncthreads();

    // ---- fc1 ----
    int r0 = wid * 16;
    int ar = r0 + (lane >> 2);
    float acc[16][4];
    #pragma unroll
    for (int nt = 0; nt < 16; nt++)
        #pragma unroll
        for (int q = 0; q < 4; q++) acc[nt][q] = 0.f;

    #pragma unroll 1
    for (int ks = 0; ks < 16; ks++) {
        int ac = ks * 16 + (lane & 3) * 2;
        uint32_t ah0 = *(uint32_t*)(sm + A_HI + ((size_t)ar * SAW + ac) * 2);
        uint32_t ah1 = *(uint32_t*)(sm + A_HI + ((size_t)(ar + 8) * SAW + ac) * 2);
        uint32_t ah2 = *(uint32_t*)(sm + A_HI + ((size_t)ar * SAW + ac + 8) * 2);
        uint32_t ah3 = *(uint32_t*)(sm + A_HI + ((size_t)(ar + 8) * SAW + ac + 8) * 2);
        uint32_t al0 = *(uint32_t*)(sm + A_LO + ((size_t)ar * SAW + ac) * 2);
        uint32_t al1 = *(uint32_t*)(sm + A_LO + ((size_t)(ar + 8) * SAW + ac) * 2);
        uint32_t al2 = *(uint32_t*)(sm + A_LO + ((size_t)ar * SAW + ac + 8) * 2);
        uint32_t al3 = *(uint32_t*)(sm + A_LO + ((size_t)(ar + 8) * SAW + ac + 8) * 2);
        #pragma unroll
        for (int nt = 0; nt < 16; nt++) {
            uint2 bh = g_B1fh[ks * 512 + nt * 32 + lane];
            uint2 bl = g_B1fl[ks * 512 + nt * 32 + lane];
            MMA_BF16(acc[nt], ah0, ah1, ah2, ah3, bh.x, bh.y);
            MMA_BF16(acc[nt], ah0, ah1, ah2, ah3, bl.x, bl.y);
            MMA_BF16(acc[nt], al0, al1, al2, al3, bh.x, bh.y);
        }
    }

    // ---- bias + relu -> A2 fragments in registers ----
    uint32_t a2h[8][4], a2l[8][4];
    #pragma unroll
    for (int k2 = 0; k2 < 8; k2++) {
        #pragma unroll
        for (int e = 0; e < 2; e++) {
            int nt = 2 * k2 + e;
            int j0 = nt * 8 + (lane & 3) * 2;
            float bb0 = (j0 < 120)     ? sb1[j0]     : 0.f;
            float bb1 = (j0 + 1 < 120) ? sb1[j0 + 1] : 0.f;
            float v0 = fmaxf(acc[nt][0] + bb0, 0.f);
            float v1 = fmaxf(acc[nt][1] + bb1, 0.f);
            float v2 = fmaxf(acc[nt][2] + bb0, 0.f);
            float v3 = fmaxf(acc[nt][3] + bb1, 0.f);
            __nv_bfloat16 h0 = __float2bfloat16(v0), h1 = __float2bfloat16(v1);
            __nv_bfloat16 h2 = __float2bfloat16(v2), h3 = __float2bfloat16(v3);
            a2h[k2][0 + 2 * e] = pkbf16(h0, h1);
            a2h[k2][1 + 2 * e] = pkbf16(h2, h3);
            a2l[k2][0 + 2 * e] = pkbf(v0 - __bfloat162float(h0), v1 - __bfloat162float(h1));
            a2l[k2][1 + 2 * e] = pkbf(v2 - __bfloat162float(h2), v3 - __bfloat162float(h3));
        }
    }

    // ---- fc2 ----
    float acc2[11][4];
    #pragma unroll
    for (int nt = 0; nt < 11; nt++)
        #pragma unroll
        for (int q = 0; q < 4; q++) acc2[nt][q] = 0.f;
    #pragma unroll 1
    for (int ks = 0; ks < 8; ks++) {
        #pragma unroll
        for (int nt = 0; nt < 11; nt++) {
            uint2 bh = g_B2fh[ks * 352 + nt * 32 + lane];
            uint2 bl = g_B2fl[ks * 352 + nt * 32 + lane];
            MMA_BF16(acc2[nt], a2h[ks][0], a2h[ks][1], a2h[ks][2], a2h[ks][3], bh.x, bh.y);
            MMA_BF16(acc2[nt], a2h[ks][0], a2h[ks][1], a2h[ks][2], a2h[ks][3], bl.x, bl.y);
            MMA_BF16(acc2[nt], a2l[ks][0], a2l[ks][1], a2l[ks][2], a2l[ks][3], bh.x, bh.y);
        }
    }

    // ---- bias + relu -> h2 fp32 smem ----
    {
        int rr = r0 + (lane >> 2);
        #pragma unroll
        for (int nt = 0; nt < 11; nt++) {
            int j0 = nt * 8 + (lane & 3) * 2;
            float bb0 = (j0 < 84)     ? sb2[j0]     : 0.f;
            float bb1 = (j0 + 1 < 84) ? sb2[j0 + 1] : 0.f;
            *(float2*)(sh2 + (size_t)rr * 90 + j0) =
                make_float2(fmaxf(acc2[nt][0] + bb0, 0.f), fmaxf(acc2[nt][1] + bb1, 0.f));
            *(float2*)(sh2 + (size_t)(rr + 8) * 90 + j0) =
                make_float2(fmaxf(acc2[nt][2] + bb0, 0.f), fmaxf(acc2[nt][3] + bb1, 0.f));
        }
    }
    __syncthreads();

    // ---- fc3 + log-softmax ----
    if (t < 64) {
        const float* hp = sh2 + (size_t)t * 90;
        float o[10];
        #pragma unroll
        for (int j = 0; j < 10; j++) o[j] = sb3[j];
        #pragma unroll 4
        for (int k = 0; k < 84; k++) {
            float hv = hp[k];
            #pragma unroll
            for (int j = 0; j < 10; j++) o[j] = fmaf(hv, sw3[k * 10 + j], o[j]);
        }
        float m = -1e30f;
        #pragma unroll
        for (int j = 0; j < 10; j++) m = fmaxf(m, o[j]);
        float s = 0.f;
        #pragma unroll
        for (int j = 0; j < 10; j++) s += __expf(o[j] - m);
        float lse = m + __logf(s);
        float* op = g_logp + ((size_t)blockIdx.x * 64 + t) * 10;
        #pragma unroll
        for (int j = 0; j < 10; j++) op[j] = o[j] - lse;
    }
}

// ---------------- probabilistic circuit (R10) ----------------
__global__ __launch_bounds__(256) void circuit_kernel(float* __restrict__ out) {
    __shared__ float lp[40];
    __shared__ float e1[100];
    __shared__ float e2[100];
    int bI = blockIdx.x;
    int t = threadIdx.x;
    if (t < 40) lp[t] = g_logp[(size_t)bI * 40 + t];
    __syncthreads();
    if (t < 100) {
        e1[t] = __expf(lp[0 + t / 10] + lp[10 + t % 10]);
    } else if (t < 200) {
        int k = t - 100;
        e2[k] = __expf(lp[20 + k / 10] + lp[30 + k % 10]);
    }
    __syncthreads();
    if (t < SUMS) {
        int lo = t > 99 ? t - 99 : 0;
        int hi = t < 99 ? t : 99;
        float s = 0.f;
        for (int i = lo; i <= hi; i++) s = fmaf(e1[i], e2[t - i], s);
        out[(size_t)bI * SUMS + t] = __logf(s);
    }
}

// ---------------- launch ----------------
extern "C" void kernel_launch(void* const* d_in, const int* in_sizes, int n_in,
                              void* d_out, int out_size) {
    const float* images = (const float*)d_in[0];
    const float* c1w    = (const float*)d_in[1];
    const float* c1b    = (const float*)d_in[2];
    const float* c2w    = (const float*)d_in[3];
    const float* c2b    = (const float*)d_in[4];
    const float* f1w    = (const float*)d_in[5];
    const float* f1b    = (const float*)d_in[6];
    const float* f2w    = (const float*)d_in[7];
    const float* f2b    = (const float*)d_in[8];
    const float* f3w    = (const float*)d_in[9];
    const float* f3b    = (const float*)d_in[10];
    float* out = (float*)d_out;

    cudaFuncSetAttribute(fc_mma_kernel, cudaFuncAttributeMaxDynamicSharedMemorySize, S_TOTAL);

    prep_kernel<<<44, 256>>>(c2w, f1w, f2w, f3w);
    conv1_kernel<<<NPAIR / 4, 576>>>(images, c1w, c1b);
    conv2_mma_kernel<<<N_IMG / 8, 256>>>(c2b);
    fc_mma_kernel<<<N_IMG / 64, 128, S_TOTAL>>>(f1b, f2b, f3b);
    circuit_kernel<<<NBATCH, 256>>>(out);
}